// round 1
// baseline (speedup 1.0000x reference)
#include <cuda_runtime.h>
#include <math.h>
#include <math_constants.h>

// Problem constants
#define NB   32
#define NT   4096
#define NQD  1024
#define NMD  512
#define NAD  128
#define NF   32
#define NKW  31
#define NPAD 15

// Score-kernel tiling
#define TILE_T 128
#define KC     32
#define ASTR   132   // padded stride for A tile (k-major)

// Scratch (device globals: no allocation allowed)
__device__ float g_pq[NB * NAD];
__device__ float g_score[NB * NT];

// ---------------------------------------------------------------------------
// Kernel 1: processed query  pq[b,a] = bq[a] + sum_q query[b,q] * Wq[q,a]
// grid: NB blocks, 128 threads
// ---------------------------------------------------------------------------
__global__ void pq_kernel(const float* __restrict__ query,
                          const float* __restrict__ Wq,
                          const float* __restrict__ bq) {
    __shared__ float qs[NQD];
    int b = blockIdx.x;
    for (int i = threadIdx.x; i < NQD; i += blockDim.x)
        qs[i] = query[b * NQD + i];
    __syncthreads();
    int a = threadIdx.x;  // 0..127
    float acc = bq[a];
#pragma unroll 8
    for (int q = 0; q < NQD; q++)
        acc = fmaf(qs[q], Wq[q * NAD + a], acc);
    g_pq[b * NAD + a] = acc;
}

// ---------------------------------------------------------------------------
// Kernel 2: fused score kernel.
// Per (b, t-tile of 128): C[128t x 128a] = memory_tile @ Wm  (K = 512)
//                                        + loc_tile @ Wl     (K = 32, fused)
// then score[b,t] = v_b + sum_a v_w[a] * tanh(C + pq[b,a] + bm[a] + bl[a])
// grid: (NT/TILE_T, NB), 256 threads; each thread owns an 8x8 register tile.
// ---------------------------------------------------------------------------
__global__ __launch_bounds__(256, 2)
void score_kernel(const float* __restrict__ memory,
                  const float* __restrict__ alignments,
                  const unsigned char* __restrict__ mask,
                  const float* __restrict__ Wm,
                  const float* __restrict__ bm,
                  const float* __restrict__ conv_w,
                  const float* __restrict__ conv_b,
                  const float* __restrict__ Wl,
                  const float* __restrict__ bl,
                  const float* __restrict__ v_w,
                  const float* __restrict__ v_b) {
    __shared__ float As[KC][ASTR];          // k-major A tile (transposed)
    __shared__ float Bs[KC][NAD];           // k-major B tile
    __shared__ float al_s[2][TILE_T + NKW - 1];  // alignment halo (158)
    __shared__ float w_s[NF * 2 * NKW];     // conv weights
    __shared__ float pqc[NAD];              // pq[b,:] + bm + bl

    const int b   = blockIdx.y;
    const int t0  = blockIdx.x * TILE_T;
    const int tid = threadIdx.x;            // 0..255
    const int tx  = tid & 15;               // a-dim group
    const int ty  = tid >> 4;               // t-dim group

    float acc[8][8];
#pragma unroll
    for (int i = 0; i < 8; i++)
#pragma unroll
        for (int j = 0; j < 8; j++) acc[i][j] = 0.f;

    // One-time tile-invariant loads
    for (int i = tid; i < NF * 2 * NKW; i += 256) w_s[i] = conv_w[i];
    for (int i = tid; i < 2 * (TILE_T + NKW - 1); i += 256) {
        int c = i / (TILE_T + NKW - 1);
        int p = i % (TILE_T + NKW - 1);
        int t = t0 - NPAD + p;
        al_s[c][p] = (t >= 0 && t < NT) ? alignments[((size_t)b * NT + t) * 2 + c] : 0.f;
    }
    if (tid < NAD) pqc[tid] = g_pq[b * NAD + tid] + bm[tid] + bl[tid];

    const float* memb = memory + (size_t)b * NT * NMD + (size_t)t0 * NMD;

    // Main K loop over memory columns (512, in chunks of 32)
    for (int k0 = 0; k0 < NMD; k0 += KC) {
        __syncthreads();
        // Load A tile (128 t x 32 k), transposed into k-major shared, float4 global reads
        for (int idx = tid; idx < TILE_T * (KC / 4); idx += 256) {
            int t  = idx >> 3;        // 0..127
            int k4 = idx & 7;         // 0..7
            float4 v = *reinterpret_cast<const float4*>(&memb[(size_t)t * NMD + k0 + k4 * 4]);
            As[k4 * 4 + 0][t] = v.x;
            As[k4 * 4 + 1][t] = v.y;
            As[k4 * 4 + 2][t] = v.z;
            As[k4 * 4 + 3][t] = v.w;
        }
        // Load B tile (32 k x 128 a)
        for (int idx = tid; idx < KC * NAD; idx += 256) {
            int k = idx >> 7, a = idx & 127;
            Bs[k][a] = Wm[(size_t)(k0 + k) * NAD + a];
        }
        __syncthreads();
#pragma unroll 8
        for (int k = 0; k < KC; k++) {
            float af[8], bf[8];
            *reinterpret_cast<float4*>(&af[0]) = *reinterpret_cast<float4*>(&As[k][ty * 8]);
            *reinterpret_cast<float4*>(&af[4]) = *reinterpret_cast<float4*>(&As[k][ty * 8 + 4]);
            *reinterpret_cast<float4*>(&bf[0]) = *reinterpret_cast<float4*>(&Bs[k][tx * 8]);
            *reinterpret_cast<float4*>(&bf[4]) = *reinterpret_cast<float4*>(&Bs[k][tx * 8 + 4]);
#pragma unroll
            for (int i = 0; i < 8; i++)
#pragma unroll
                for (int j = 0; j < 8; j++)
                    acc[i][j] = fmaf(af[i], bf[j], acc[i][j]);
        }
    }

    // Fused location-feature chunk: As := loc (F x TILE_T), Bs := Wl (F x AD)
    __syncthreads();
    for (int idx = tid; idx < NF * TILE_T; idx += 256) {
        int f = idx & 31;
        int t = idx >> 5;             // 0..127
        float v = conv_b[f];
        const float* wf = &w_s[f * 2 * NKW];
#pragma unroll
        for (int c = 0; c < 2; c++) {
#pragma unroll
            for (int k = 0; k < NKW; k++)
                v = fmaf(al_s[c][t + k], wf[c * NKW + k], v);
        }
        As[f][t] = v;
    }
    for (int idx = tid; idx < NF * NAD; idx += 256) {
        int f = idx >> 7, a = idx & 127;
        Bs[f][a] = Wl[f * NAD + a];
    }
    __syncthreads();
#pragma unroll 8
    for (int k = 0; k < KC; k++) {
        float af[8], bf[8];
        *reinterpret_cast<float4*>(&af[0]) = *reinterpret_cast<float4*>(&As[k][ty * 8]);
        *reinterpret_cast<float4*>(&af[4]) = *reinterpret_cast<float4*>(&As[k][ty * 8 + 4]);
        *reinterpret_cast<float4*>(&bf[0]) = *reinterpret_cast<float4*>(&Bs[k][tx * 8]);
        *reinterpret_cast<float4*>(&bf[4]) = *reinterpret_cast<float4*>(&Bs[k][tx * 8 + 4]);
#pragma unroll
        for (int i = 0; i < 8; i++)
#pragma unroll
            for (int j = 0; j < 8; j++)
                acc[i][j] = fmaf(af[i], bf[j], acc[i][j]);
    }

    // Epilogue: tanh, v-dot, reduce across the 16 a-groups (half-warp shuffle)
    float vb = *v_b;
    float vw[8], pc[8];
#pragma unroll
    for (int j = 0; j < 8; j++) {
        vw[j] = v_w[tx * 8 + j];
        pc[j] = pqc[tx * 8 + j];
    }
#pragma unroll
    for (int i = 0; i < 8; i++) {
        float s = 0.f;
#pragma unroll
        for (int j = 0; j < 8; j++)
            s = fmaf(vw[j], tanhf(acc[i][j] + pc[j]), s);
        // threads sharing a t-row are 16 consecutive lanes of a warp
        s += __shfl_down_sync(0xffffffffu, s, 8, 16);
        s += __shfl_down_sync(0xffffffffu, s, 4, 16);
        s += __shfl_down_sync(0xffffffffu, s, 2, 16);
        s += __shfl_down_sync(0xffffffffu, s, 1, 16);
        if (tx == 0) {
            int t = t0 + ty * 8 + i;
            float sc = s + vb;
            if (mask[(size_t)b * NT + t]) sc = -CUDART_INF_F;
            g_score[(size_t)b * NT + t] = sc;
        }
    }
}

// ---------------------------------------------------------------------------
// Kernel 3: row softmax over T -> alignment (written straight into d_out slice)
// grid: NB blocks, 256 threads
// ---------------------------------------------------------------------------
__global__ void softmax_kernel(float* __restrict__ align_out) {
    int b = blockIdx.x;
    int tid = threadIdx.x;
    __shared__ float red[256];

    float m = -CUDART_INF_F;
    for (int t = tid; t < NT; t += 256) m = fmaxf(m, g_score[(size_t)b * NT + t]);
    red[tid] = m;
    __syncthreads();
    for (int s = 128; s > 0; s >>= 1) {
        if (tid < s) red[tid] = fmaxf(red[tid], red[tid + s]);
        __syncthreads();
    }
    m = red[0];
    __syncthreads();

    float sum = 0.f;
    for (int t = tid; t < NT; t += 256) {
        float e = expf(g_score[(size_t)b * NT + t] - m);
        align_out[(size_t)b * NT + t] = e;
        sum += e;
    }
    red[tid] = sum;
    __syncthreads();
    for (int s = 128; s > 0; s >>= 1) {
        if (tid < s) red[tid] += red[tid + s];
        __syncthreads();
    }
    float inv = 1.0f / red[0];
    for (int t = tid; t < NT; t += 256) align_out[(size_t)b * NT + t] *= inv;
}

// ---------------------------------------------------------------------------
// Kernel 4a: zero context region of d_out
// ---------------------------------------------------------------------------
__global__ void ctx_init_kernel(float* __restrict__ ctx) {
    ctx[blockIdx.x * NMD + threadIdx.x] = 0.f;
}

// Kernel 4b: context[b,m] += sum over t-chunk of align[b,t]*memory[b,t,m]
// grid: (T/128 chunks, NB), 512 threads (one per m)
// ---------------------------------------------------------------------------
#define TCH 128
__global__ void context_kernel(const float* __restrict__ memory,
                               const float* __restrict__ align,
                               float* __restrict__ ctx) {
    int b  = blockIdx.y;
    int tc = blockIdx.x;
    int m  = threadIdx.x;  // 0..511

    __shared__ float al[TCH];
    for (int i = threadIdx.x; i < TCH; i += 512)
        al[i] = align[(size_t)b * NT + tc * TCH + i];
    __syncthreads();

    const float* mb = memory + (size_t)b * NT * NMD + (size_t)tc * TCH * NMD;
    float acc = 0.f;
#pragma unroll 4
    for (int t = 0; t < TCH; t++)
        acc = fmaf(al[t], mb[(size_t)t * NMD + m], acc);
    atomicAdd(&ctx[b * NMD + m], acc);
}

// ---------------------------------------------------------------------------
// kernel_launch
// Input order: query, memory, alignments, mask, Wq, bq, Wm, bm,
//              conv_w, conv_b, Wl, bl, v_w, v_b
// Output: [context (32*512) | alignment (32*4096)]
// ---------------------------------------------------------------------------
extern "C" void kernel_launch(void* const* d_in, const int* in_sizes, int n_in,
                              void* d_out, int out_size) {
    const float* query      = (const float*)d_in[0];
    const float* memory     = (const float*)d_in[1];
    const float* alignments = (const float*)d_in[2];
    const unsigned char* mask = (const unsigned char*)d_in[3];
    const float* Wq     = (const float*)d_in[4];
    const float* bq     = (const float*)d_in[5];
    const float* Wm     = (const float*)d_in[6];
    const float* bm     = (const float*)d_in[7];
    const float* conv_w = (const float*)d_in[8];
    const float* conv_b = (const float*)d_in[9];
    const float* Wl     = (const float*)d_in[10];
    const float* bl     = (const float*)d_in[11];
    const float* v_w    = (const float*)d_in[12];
    const float* v_b    = (const float*)d_in[13];

    float* out       = (float*)d_out;
    float* out_ctx   = out;                 // [NB, NMD]
    float* out_align = out + NB * NMD;      // [NB, NT]

    ctx_init_kernel<<<NB, NMD>>>(out_ctx);
    pq_kernel<<<NB, NAD>>>(query, Wq, bq);
    score_kernel<<<dim3(NT / TILE_T, NB), 256>>>(memory, alignments, mask,
                                                 Wm, bm, conv_w, conv_b,
                                                 Wl, bl, v_w, v_b);
    softmax_kernel<<<NB, 256>>>(out_align);
    context_kernel<<<dim3(NT / TCH, NB), 512>>>(memory, out_align, out_ctx);
}

// round 5
// speedup vs baseline: 2.0198x; 2.0198x over previous
#include <cuda_runtime.h>
#include <cuda_bf16.h>
#include <math.h>
#include <math_constants.h>
#include <stdint.h>

// Problem constants
#define NB   32
#define NT   4096
#define NQD  1024
#define NMD  512
#define NAD  128
#define NF   32
#define NKW  31
#define NPAD 15

// Score-kernel tiling
#define TILE_T  128
#define KCH     32          // K per chunk (bf16 elems); loc chunk is exactly 32
#define NCHUNK  16          // 16 memory chunks; chunk 16 == loc chunk
#define ASTR    36          // padded row stride in elems (72 B)

// ---------------------------------------------------------------------------
// Device scratch (no allocation allowed). uint4-typed => 16B alignment by type.
// ---------------------------------------------------------------------------
__device__ float g_pq[NB * NAD];
__device__ float g_score[NB * NT];
// Pre-split B operands: [chunk][a(128)][k(32)] bf16 packed in uint4 (8 shorts)
__device__ uint4 g_Bhi4[NCHUNK * TILE_T * KCH / 8];
__device__ uint4 g_Blo4[NCHUNK * TILE_T * KCH / 8];
__device__ uint4 g_Wlhi4[TILE_T * KCH / 8];
__device__ uint4 g_Wllo4[TILE_T * KCH / 8];

// ---------------------------------------------------------------------------
// Helpers
// ---------------------------------------------------------------------------
__device__ __forceinline__ void mma16816(float* c, const uint32_t* a,
                                         const uint32_t* b) {
    asm volatile(
        "mma.sync.aligned.m16n8k16.row.col.f32.bf16.bf16.f32 "
        "{%0,%1,%2,%3}, {%4,%5,%6,%7}, {%8,%9}, {%0,%1,%2,%3};"
        : "+f"(c[0]), "+f"(c[1]), "+f"(c[2]), "+f"(c[3])
        : "r"(a[0]), "r"(a[1]), "r"(a[2]), "r"(a[3]), "r"(b[0]), "r"(b[1]));
}

__device__ __forceinline__ void split_bf16(float x, unsigned short& h,
                                           unsigned short& l) {
    __nv_bfloat16 hb = __float2bfloat16(x);
    float hf = __bfloat162float(hb);
    __nv_bfloat16 lb = __float2bfloat16(x - hf);
    h = ((__nv_bfloat16_raw)hb).x;
    l = ((__nv_bfloat16_raw)lb).x;
}

// ---------------------------------------------------------------------------
// Prep: split Wm / Wl into bf16 hi/lo, [chunk][a][k] linear layout
// ---------------------------------------------------------------------------
__global__ void prep_kernel(const float* __restrict__ Wm,
                            const float* __restrict__ Wl) {
    int idx = blockIdx.x * blockDim.x + threadIdx.x;
    unsigned short* bhi = (unsigned short*)g_Bhi4;
    unsigned short* blo = (unsigned short*)g_Blo4;
    unsigned short* whi = (unsigned short*)g_Wlhi4;
    unsigned short* wlo = (unsigned short*)g_Wllo4;
    if (idx < NMD * NAD) {
        int k = idx >> 7, a = idx & 127;       // k<512, a<128
        int c = k >> 5, kk = k & 31;
        unsigned short h, l;
        split_bf16(Wm[k * NAD + a], h, l);
        int dst = c * (TILE_T * KCH) + a * KCH + kk;
        bhi[dst] = h;
        blo[dst] = l;
    } else if (idx < NMD * NAD + TILE_T * KCH) {
        int r = idx - NMD * NAD;               // a*32 + kk
        int a = r >> 5, kk = r & 31;
        unsigned short h, l;
        split_bf16(Wl[kk * NAD + a], h, l);    // kk < 32 == NF
        whi[a * KCH + kk] = h;
        wlo[a * KCH + kk] = l;
    }
}

// ---------------------------------------------------------------------------
// Kernel 1: processed query
// ---------------------------------------------------------------------------
__global__ void pq_kernel(const float* __restrict__ query,
                          const float* __restrict__ Wq,
                          const float* __restrict__ bq) {
    __shared__ float qs[NQD];
    int b = blockIdx.x;
    for (int i = threadIdx.x; i < NQD; i += blockDim.x)
        qs[i] = query[b * NQD + i];
    __syncthreads();
    int a = threadIdx.x;
    float acc = bq[a];
#pragma unroll 8
    for (int q = 0; q < NQD; q++)
        acc = fmaf(qs[q], Wq[q * NAD + a], acc);
    g_pq[b * NAD + a] = acc;
}

// ---------------------------------------------------------------------------
// Kernel 2: fused score kernel on tensor cores (mma.sync bf16, hi/lo split).
// D[128t x 128a] = mem@Wm (K=512) + loc@Wl (K=32), then
// score = v_b + sum_a v_w[a]*tanh(D + pq + bm + bl), mask -> g_score.
// 8 warps: warp (wm, wn) owns a 64t x 32a sub-tile. Static shared only.
// ---------------------------------------------------------------------------
__global__ __launch_bounds__(256, 2)
void score_kernel(const float* __restrict__ memory,
                  const float* __restrict__ alignments,
                  const unsigned char* __restrict__ mask,
                  const float* __restrict__ bm,
                  const float* __restrict__ conv_w,
                  const float* __restrict__ conv_b,
                  const float* __restrict__ bl,
                  const float* __restrict__ v_w,
                  const float* __restrict__ v_b) {
    // Static shared: compiler-verified layout (total 48240 B <= 48 KB)
    __shared__ __align__(16) unsigned short sAhi[TILE_T * ASTR];
    __shared__ __align__(16) unsigned short sAlo[TILE_T * ASTR];
    __shared__ __align__(16) unsigned short sBhi[TILE_T * ASTR];
    __shared__ __align__(16) unsigned short sBlo[TILE_T * ASTR];
    __shared__ float pqc[NAD];
    __shared__ float vw_s[NAD];
    __shared__ float al_s[2][TILE_T + NKW - 1];
    __shared__ float w_s[NF * 2 * NKW];        // 1984 floats (7936 B)
    __shared__ float cb_s[NF];
    __shared__ float part[2][TILE_T];

    const int tid  = threadIdx.x;
    const int lane = tid & 31;
    const int wid  = tid >> 5;
    const int wm   = wid >> 2;       // 0..1 (t-halves)
    const int wn   = wid & 3;        // 0..3 (a-quarters)
    const int g    = lane >> 2;      // groupID
    const int tg   = lane & 3;       // thread-in-group
    const int b    = blockIdx.y;
    const int t0   = blockIdx.x * TILE_T;

    for (int i = tid; i < NF * 2 * NKW; i += 256) w_s[i] = conv_w[i];
    for (int i = tid; i < 2 * (TILE_T + NKW - 1); i += 256) {
        int c = i / (TILE_T + NKW - 1);
        int p = i % (TILE_T + NKW - 1);
        int t = t0 - NPAD + p;
        al_s[c][p] = (t >= 0 && t < NT)
                   ? alignments[((size_t)b * NT + t) * 2 + c] : 0.f;
    }
    if (tid < NAD) {
        pqc[tid]  = g_pq[b * NAD + tid] + bm[tid] + bl[tid];
        vw_s[tid] = v_w[tid];
    }
    if (tid < NF) cb_s[tid] = conv_b[tid];

    const float* memb = memory + ((size_t)b * NT + t0) * NMD;

    float acc[4][4][4];
#pragma unroll
    for (int mi = 0; mi < 4; mi++)
#pragma unroll
        for (int ni = 0; ni < 4; ni++)
#pragma unroll
            for (int j = 0; j < 4; j++) acc[mi][ni][j] = 0.f;

    for (int c = 0; c <= NCHUNK; c++) {
        __syncthreads();   // previous chunk's MMAs done reading smem

        if (c < NCHUNK) {
            // A: convert memory chunk [128t x 32k] fp32 -> bf16 hi/lo.
            // 1024 units of 4 elems; uint2 stores (8B-aligned: rows are 72B).
#pragma unroll
            for (int u = 0; u < 4; u++) {
                int unit = tid + u * 256;          // 0..1023
                int t = unit >> 3, gg = unit & 7;  // 4-elem groups
                const float* src = memb + (size_t)t * NMD + c * KCH + gg * 4;
                float4 v = *(const float4*)src;
                unsigned short h0, l0, h1, l1, h2, l2, h3, l3;
                split_bf16(v.x, h0, l0);
                split_bf16(v.y, h1, l1);
                split_bf16(v.z, h2, l2);
                split_bf16(v.w, h3, l3);
                int off = t * ASTR + gg * 4;
                *(uint2*)&sAhi[off] = make_uint2(
                    (uint32_t)h0 | ((uint32_t)h1 << 16),
                    (uint32_t)h2 | ((uint32_t)h3 << 16));
                *(uint2*)&sAlo[off] = make_uint2(
                    (uint32_t)l0 | ((uint32_t)l1 << 16),
                    (uint32_t)l2 | ((uint32_t)l3 << 16));
            }
            // B: copy Wm chunk (512 uint4 each) into padded rows
            const uint4* shp = g_Bhi4 + c * 512;
            const uint4* slp = g_Blo4 + c * 512;
#pragma unroll
            for (int u = 0; u < 2; u++) {
                int i = tid + u * 256;             // 0..511
                int a = i >> 2, gg = i & 3;        // 8-elem groups
                int off = a * ASTR + gg * 8;
                uint4 vh = shp[i], vl = slp[i];
                *(uint2*)&sBhi[off]     = make_uint2(vh.x, vh.y);
                *(uint2*)&sBhi[off + 4] = make_uint2(vh.z, vh.w);
                *(uint2*)&sBlo[off]     = make_uint2(vl.x, vl.y);
                *(uint2*)&sBlo[off + 4] = make_uint2(vl.z, vl.w);
            }
        } else {
            // loc chunk: conv -> bf16 hi/lo (K = 32 exactly)
            for (int idx = tid; idx < TILE_T * NF; idx += 256) {
                int t = idx >> 5, f = idx & 31;
                float v = cb_s[f];
                const float* wf = &w_s[f * 2 * NKW];
#pragma unroll
                for (int cc = 0; cc < 2; cc++)
#pragma unroll
                    for (int k = 0; k < NKW; k++)
                        v = fmaf(al_s[cc][t + k], wf[cc * NKW + k], v);
                unsigned short h, l;
                split_bf16(v, h, l);
                sAhi[t * ASTR + f] = h;
                sAlo[t * ASTR + f] = l;
            }
            const uint4* shp = g_Wlhi4;
            const uint4* slp = g_Wllo4;
#pragma unroll
            for (int u = 0; u < 2; u++) {
                int i = tid + u * 256;
                int a = i >> 2, gg = i & 3;
                int off = a * ASTR + gg * 8;
                uint4 vh = shp[i], vl = slp[i];
                *(uint2*)&sBhi[off]     = make_uint2(vh.x, vh.y);
                *(uint2*)&sBhi[off + 4] = make_uint2(vh.z, vh.w);
                *(uint2*)&sBlo[off]     = make_uint2(vl.x, vl.y);
                *(uint2*)&sBlo[off + 4] = make_uint2(vl.z, vl.w);
            }
        }
        __syncthreads();

        // Two K16 steps per chunk; plain LDS.32 fragment loads.
#pragma unroll
        for (int ks = 0; ks < 2; ks++) {
            const int k0   = ks * 16;
            const int col0 = k0 + tg * 2;
            const int col1 = col0 + 8;

            uint32_t bh[8], blr[8];
#pragma unroll
            for (int ni = 0; ni < 4; ni++) {
                int n = wn * 32 + ni * 8 + g;
                bh[ni * 2]      = *(const uint32_t*)&sBhi[n * ASTR + col0];
                bh[ni * 2 + 1]  = *(const uint32_t*)&sBhi[n * ASTR + col1];
                blr[ni * 2]     = *(const uint32_t*)&sBlo[n * ASTR + col0];
                blr[ni * 2 + 1] = *(const uint32_t*)&sBlo[n * ASTR + col1];
            }
#pragma unroll
            for (int mi = 0; mi < 4; mi++) {
                int row0 = wm * 64 + mi * 16 + g;
                int row1 = row0 + 8;
                uint32_t ah[4], alr[4];
                ah[0]  = *(const uint32_t*)&sAhi[row0 * ASTR + col0];
                ah[1]  = *(const uint32_t*)&sAhi[row1 * ASTR + col0];
                ah[2]  = *(const uint32_t*)&sAhi[row0 * ASTR + col1];
                ah[3]  = *(const uint32_t*)&sAhi[row1 * ASTR + col1];
                alr[0] = *(const uint32_t*)&sAlo[row0 * ASTR + col0];
                alr[1] = *(const uint32_t*)&sAlo[row1 * ASTR + col0];
                alr[2] = *(const uint32_t*)&sAlo[row0 * ASTR + col1];
                alr[3] = *(const uint32_t*)&sAlo[row1 * ASTR + col1];
#pragma unroll
                for (int ni = 0; ni < 4; ni++) {
                    mma16816(acc[mi][ni], ah,  &bh[ni * 2]);
                    mma16816(acc[mi][ni], ah,  &blr[ni * 2]);
                    mma16816(acc[mi][ni], alr, &bh[ni * 2]);
                }
            }
        }
    }

    // Epilogue: tanh + v-dot, reduce over tg lanes, then 2-stage over wn warps
    float s0[4], s1[4];
#pragma unroll
    for (int mi = 0; mi < 4; mi++) {
        float p0 = 0.f, p1 = 0.f;
#pragma unroll
        for (int ni = 0; ni < 4; ni++) {
#pragma unroll
            for (int j = 0; j < 2; j++) {
                int cdx = wn * 32 + ni * 8 + tg * 2 + j;
                p0 = fmaf(vw_s[cdx], tanhf(acc[mi][ni][j]     + pqc[cdx]), p0);
                p1 = fmaf(vw_s[cdx], tanhf(acc[mi][ni][2 + j] + pqc[cdx]), p1);
            }
        }
        p0 += __shfl_xor_sync(0xffffffffu, p0, 1);
        p0 += __shfl_xor_sync(0xffffffffu, p0, 2);
        p1 += __shfl_xor_sync(0xffffffffu, p1, 1);
        p1 += __shfl_xor_sync(0xffffffffu, p1, 2);
        s0[mi] = p0;
        s1[mi] = p1;
    }
    __syncthreads();   // tiles no longer needed;部 part[] is separate anyway
    if (wn < 2 && tg == 0) {
#pragma unroll
        for (int mi = 0; mi < 4; mi++) {
            int r = wm * 64 + mi * 16 + g;
            part[wn][r]     = s0[mi];
            part[wn][r + 8] = s1[mi];
        }
    }
    __syncthreads();
    if (wn >= 2 && tg == 0) {
#pragma unroll
        for (int mi = 0; mi < 4; mi++) {
            int r = wm * 64 + mi * 16 + g;
            part[wn - 2][r]     += s0[mi];
            part[wn - 2][r + 8] += s1[mi];
        }
    }
    __syncthreads();

    if (tid < TILE_T) {
        float sc = part[0][tid] + part[1][tid] + v_b[0];
        if (mask[(size_t)b * NT + t0 + tid]) sc = -CUDART_INF_F;
        g_score[(size_t)b * NT + t0 + tid] = sc;
    }
}

// ---------------------------------------------------------------------------
// Kernel 3: row softmax over T -> alignment (into d_out slice)
// ---------------------------------------------------------------------------
__global__ void softmax_kernel(float* __restrict__ align_out) {
    int b = blockIdx.x;
    int tid = threadIdx.x;
    __shared__ float red[256];

    float m = -CUDART_INF_F;
    for (int t = tid; t < NT; t += 256) m = fmaxf(m, g_score[(size_t)b * NT + t]);
    red[tid] = m;
    __syncthreads();
    for (int s = 128; s > 0; s >>= 1) {
        if (tid < s) red[tid] = fmaxf(red[tid], red[tid + s]);
        __syncthreads();
    }
    m = red[0];
    __syncthreads();

    float sum = 0.f;
    for (int t = tid; t < NT; t += 256) {
        float e = expf(g_score[(size_t)b * NT + t] - m);
        align_out[(size_t)b * NT + t] = e;
        sum += e;
    }
    red[tid] = sum;
    __syncthreads();
    for (int s = 128; s > 0; s >>= 1) {
        if (tid < s) red[tid] += red[tid + s];
        __syncthreads();
    }
    float inv = 1.0f / red[0];
    for (int t = tid; t < NT; t += 256) align_out[(size_t)b * NT + t] *= inv;
}

// ---------------------------------------------------------------------------
// Kernel 4: context
// ---------------------------------------------------------------------------
__global__ void ctx_init_kernel(float* __restrict__ ctx) {
    ctx[blockIdx.x * NMD + threadIdx.x] = 0.f;
}

#define TCH 128
__global__ void context_kernel(const float* __restrict__ memory,
                               const float* __restrict__ align,
                               float* __restrict__ ctx) {
    int b  = blockIdx.y;
    int tc = blockIdx.x;
    int m  = threadIdx.x;

    __shared__ float al[TCH];
    for (int i = threadIdx.x; i < TCH; i += 512)
        al[i] = align[(size_t)b * NT + tc * TCH + i];
    __syncthreads();

    const float* mb = memory + (size_t)b * NT * NMD + (size_t)tc * TCH * NMD;
    float acc = 0.f;
#pragma unroll 4
    for (int t = 0; t < TCH; t++)
        acc = fmaf(al[t], mb[(size_t)t * NMD + m], acc);
    atomicAdd(&ctx[b * NMD + m], acc);
}

// ---------------------------------------------------------------------------
// kernel_launch
// ---------------------------------------------------------------------------
extern "C" void kernel_launch(void* const* d_in, const int* in_sizes, int n_in,
                              void* d_out, int out_size) {
    const float* query      = (const float*)d_in[0];
    const float* memory     = (const float*)d_in[1];
    const float* alignments = (const float*)d_in[2];
    const unsigned char* mask = (const unsigned char*)d_in[3];
    const float* Wq     = (const float*)d_in[4];
    const float* bq     = (const float*)d_in[5];
    const float* Wm     = (const float*)d_in[6];
    const float* bm     = (const float*)d_in[7];
    const float* conv_w = (const float*)d_in[8];
    const float* conv_b = (const float*)d_in[9];
    const float* Wl     = (const float*)d_in[10];
    const float* bl     = (const float*)d_in[11];
    const float* v_w    = (const float*)d_in[12];
    const float* v_b    = (const float*)d_in[13];

    float* out       = (float*)d_out;
    float* out_ctx   = out;                // [NB, NMD]
    float* out_align = out + NB * NMD;     // [NB, NT]

    ctx_init_kernel<<<NB, NMD>>>(out_ctx);
    prep_kernel<<<(NMD * NAD + TILE_T * KCH + 255) / 256, 256>>>(Wm, Wl);
    pq_kernel<<<NB, NAD>>>(query, Wq, bq);
    score_kernel<<<dim3(NT / TILE_T, NB), 256>>>(
        memory, alignments, mask, bm, conv_w, conv_b, bl, v_w, v_b);
    softmax_kernel<<<NB, 256>>>(out_align);
    context_kernel<<<dim3(NT / TCH, NB), 512>>>(memory, out_align, out_ctx);
}

// round 6
// speedup vs baseline: 2.5720x; 1.2734x over previous
#include <cuda_runtime.h>
#include <cuda_bf16.h>
#include <math.h>
#include <math_constants.h>
#include <stdint.h>

// Problem constants
#define NB   32
#define NT   4096
#define NQD  1024
#define NMD  512
#define NAD  128
#define NF   32
#define NKW  31
#define NPAD 15

// Score-kernel tiling
#define TILE_T  128
#define KCH     32          // K per chunk; loc chunk (Wl, K=32) is a regular chunk
#define NCHUNK  16          // memory chunks; chunk index 16 == loc chunk
#define ASTR    40          // padded row stride in elems (80 B, 16B-multiple for ldmatrix)

// ---------------------------------------------------------------------------
// Device scratch (no allocation allowed). uint4-typed => 16B alignment by type.
// ---------------------------------------------------------------------------
__device__ alignas(16) float g_pq[NB * NAD];
__device__ alignas(16) float g_score[NB * NT];
// Pre-split B operands: [chunk][a(128)][k(32)] bf16 packed as uint4 (8 shorts)
__device__ uint4 g_Bhi4[NCHUNK * TILE_T * KCH / 8];
__device__ uint4 g_Blo4[NCHUNK * TILE_T * KCH / 8];
__device__ uint4 g_Wlhi4[TILE_T * KCH / 8];
__device__ uint4 g_Wllo4[TILE_T * KCH / 8];

// ---------------------------------------------------------------------------
// Shared-memory layout for score kernel: compiler-verified struct.
// ---------------------------------------------------------------------------
struct ScoreSmem {
    alignas(16) unsigned short Ahi[TILE_T * ASTR];
    alignas(16) unsigned short Alo[TILE_T * ASTR];
    alignas(16) unsigned short Bhi[TILE_T * ASTR];
    alignas(16) unsigned short Blo[TILE_T * ASTR];
    float pqc[NAD];
    float vw[NAD];
    float al[2][TILE_T + NKW - 1];
    float ws[NF * 2 * NKW];     // 1984 floats
    float cb[NF];
    float part[2][TILE_T];
};
static_assert(sizeof(ScoreSmem) <= 53248, "smem overflow");

// ---------------------------------------------------------------------------
// Helpers
// ---------------------------------------------------------------------------
__device__ __forceinline__ uint32_t smem_u32(const void* p) {
    uint32_t r;
    asm("{ .reg .u64 t; cvta.to.shared.u64 t, %1; cvt.u32.u64 %0, t; }"
        : "=r"(r) : "l"(p));
    return r;
}

__device__ __forceinline__ void ldsm4(uint32_t* r, uint32_t addr) {
    asm volatile("ldmatrix.sync.aligned.m8n8.x4.shared.b16 {%0,%1,%2,%3}, [%4];"
                 : "=r"(r[0]), "=r"(r[1]), "=r"(r[2]), "=r"(r[3]) : "r"(addr));
}

__device__ __forceinline__ void mma16816(float* c, const uint32_t* a,
                                         const uint32_t* b) {
    asm volatile(
        "mma.sync.aligned.m16n8k16.row.col.f32.bf16.bf16.f32 "
        "{%0,%1,%2,%3}, {%4,%5,%6,%7}, {%8,%9}, {%0,%1,%2,%3};"
        : "+f"(c[0]), "+f"(c[1]), "+f"(c[2]), "+f"(c[3])
        : "r"(a[0]), "r"(a[1]), "r"(a[2]), "r"(a[3]), "r"(b[0]), "r"(b[1]));
}

__device__ __forceinline__ void split_bf16(float x, unsigned short& h,
                                           unsigned short& l) {
    __nv_bfloat16 hb = __float2bfloat16(x);
    float hf = __bfloat162float(hb);
    __nv_bfloat16 lb = __float2bfloat16(x - hf);
    h = ((__nv_bfloat16_raw)hb).x;
    l = ((__nv_bfloat16_raw)lb).x;
}

// ---------------------------------------------------------------------------
// Prep: split Wm / Wl into bf16 hi/lo, [chunk][a][k] linear layout
// ---------------------------------------------------------------------------
__global__ void prep_kernel(const float* __restrict__ Wm,
                            const float* __restrict__ Wl) {
    int idx = blockIdx.x * blockDim.x + threadIdx.x;
    unsigned short* bhi = (unsigned short*)g_Bhi4;
    unsigned short* blo = (unsigned short*)g_Blo4;
    unsigned short* whi = (unsigned short*)g_Wlhi4;
    unsigned short* wlo = (unsigned short*)g_Wllo4;
    if (idx < NMD * NAD) {
        int k = idx >> 7, a = idx & 127;
        int c = k >> 5, kk = k & 31;
        unsigned short h, l;
        split_bf16(Wm[k * NAD + a], h, l);
        int dst = c * (TILE_T * KCH) + a * KCH + kk;
        bhi[dst] = h;
        blo[dst] = l;
    } else if (idx < NMD * NAD + TILE_T * KCH) {
        int r = idx - NMD * NAD;
        int a = r >> 5, kk = r & 31;
        unsigned short h, l;
        split_bf16(Wl[kk * NAD + a], h, l);   // kk < 32 == NF
        whi[a * KCH + kk] = h;
        wlo[a * KCH + kk] = l;
    }
}

// ---------------------------------------------------------------------------
// Kernel 1: processed query (split-K over 2 thread groups)
// ---------------------------------------------------------------------------
__global__ void pq_kernel(const float* __restrict__ query,
                          const float* __restrict__ Wq,
                          const float* __restrict__ bq) {
    __shared__ float qs[NQD];
    __shared__ float partial[256];
    int b = blockIdx.x;
    int tid = threadIdx.x;      // 0..255
    for (int i = tid; i < NQD; i += 256)
        qs[i] = query[b * NQD + i];
    __syncthreads();
    int a = tid & 127;
    int h = tid >> 7;           // 0..1 k-half
    float acc = 0.f;
    int q0 = h * (NQD / 2);
#pragma unroll 8
    for (int q = 0; q < NQD / 2; q++)
        acc = fmaf(qs[q0 + q], Wq[(q0 + q) * NAD + a], acc);
    partial[tid] = acc;
    __syncthreads();
    if (tid < 128)
        g_pq[b * NAD + a] = bq[a] + partial[tid] + partial[tid + 128];
}

// ---------------------------------------------------------------------------
// Kernel 2: fused score kernel on tensor cores (mma.sync bf16, hi/lo split,
// ldmatrix fragment loads). 8 warps: warp (wm, wn) owns a 64t x 32a sub-tile.
// ---------------------------------------------------------------------------
__global__ __launch_bounds__(256, 2)
void score_kernel(const float* __restrict__ memory,
                  const float* __restrict__ alignments,
                  const unsigned char* __restrict__ mask,
                  const float* __restrict__ bm,
                  const float* __restrict__ conv_w,
                  const float* __restrict__ conv_b,
                  const float* __restrict__ bl,
                  const float* __restrict__ v_w,
                  const float* __restrict__ v_b) {
    extern __shared__ char smem_raw[];
    ScoreSmem& S = *reinterpret_cast<ScoreSmem*>(smem_raw);

    const int tid  = threadIdx.x;
    const int lane = tid & 31;
    const int wid  = tid >> 5;
    const int wm   = wid >> 2;       // 0..1 (t-halves)
    const int wn   = wid & 3;        // 0..3 (a-quarters)
    const int g    = lane >> 2;      // 0..7
    const int tg   = lane & 3;       // 0..3
    const int b    = blockIdx.y;
    const int t0   = blockIdx.x * TILE_T;

    for (int i = tid; i < NF * 2 * NKW; i += 256) S.ws[i] = conv_w[i];
    for (int i = tid; i < 2 * (TILE_T + NKW - 1); i += 256) {
        int c = i / (TILE_T + NKW - 1);
        int p = i % (TILE_T + NKW - 1);
        int t = t0 - NPAD + p;
        S.al[c][p] = (t >= 0 && t < NT)
                   ? alignments[((size_t)b * NT + t) * 2 + c] : 0.f;
    }
    if (tid < NAD) {
        S.pqc[tid] = g_pq[b * NAD + tid] + bm[tid] + bl[tid];
        S.vw[tid]  = v_w[tid];
    }
    if (tid < NF) S.cb[tid] = conv_b[tid];

    const float* memb = memory + ((size_t)b * NT + t0) * NMD;

    // smem base addresses for ldmatrix
    const uint32_t uAhi = smem_u32(S.Ahi);
    const uint32_t uAlo = smem_u32(S.Alo);
    const uint32_t uBhi = smem_u32(S.Bhi);
    const uint32_t uBlo = smem_u32(S.Blo);

    float acc[4][4][4];
#pragma unroll
    for (int mi = 0; mi < 4; mi++)
#pragma unroll
        for (int ni = 0; ni < 4; ni++)
#pragma unroll
            for (int j = 0; j < 4; j++) acc[mi][ni][j] = 0.f;

    // ldmatrix per-lane addressing (element offsets)
    const int aRow  = wm * 64 + (lane & 15);
    const int aColX = (lane >> 4) * 8;
    const int bRow  = wn * 32 + ((lane >> 4) << 3) + (lane & 7);
    const int bColX = ((lane >> 3) & 1) * 8;

    for (int c = 0; c <= NCHUNK; c++) {
        __syncthreads();   // previous chunk's MMAs done reading smem

        if (c < NCHUNK) {
            // A: convert memory chunk [128t x 32k] fp32 -> bf16 hi/lo,
            // 512 units of 8 elems; 16B-aligned uint4 stores.
#pragma unroll
            for (int u = 0; u < 2; u++) {
                int unit = tid + u * 256;          // 0..511
                int t = unit >> 2, gg = unit & 3;  // 8-elem groups
                const float* src = memb + (size_t)t * NMD + c * KCH + gg * 8;
                float4 v0 = *(const float4*)src;
                float4 v1 = *(const float4*)(src + 4);
                float f[8] = {v0.x, v0.y, v0.z, v0.w, v1.x, v1.y, v1.z, v1.w};
                uint32_t hw[4], lw[4];
#pragma unroll
                for (int j = 0; j < 4; j++) {
                    unsigned short h0, l0, h1, l1;
                    split_bf16(f[2 * j],     h0, l0);
                    split_bf16(f[2 * j + 1], h1, l1);
                    hw[j] = (uint32_t)h0 | ((uint32_t)h1 << 16);
                    lw[j] = (uint32_t)l0 | ((uint32_t)l1 << 16);
                }
                int off = t * ASTR + gg * 8;       // bytes: t*80 + gg*16 (16B-aligned)
                *(uint4*)&S.Ahi[off] = make_uint4(hw[0], hw[1], hw[2], hw[3]);
                *(uint4*)&S.Alo[off] = make_uint4(lw[0], lw[1], lw[2], lw[3]);
            }
            // B: copy Wm chunk (512 uint4 each) into padded rows
            const uint4* shp = g_Bhi4 + c * 512;
            const uint4* slp = g_Blo4 + c * 512;
#pragma unroll
            for (int u = 0; u < 2; u++) {
                int i = tid + u * 256;             // 0..511
                int a = i >> 2, gg = i & 3;
                int off = a * ASTR + gg * 8;
                *(uint4*)&S.Bhi[off] = shp[i];
                *(uint4*)&S.Blo[off] = slp[i];
            }
        } else {
            // loc chunk: conv -> bf16 hi/lo (K = 32 exactly)
            for (int idx = tid; idx < TILE_T * NF; idx += 256) {
                int t = idx >> 5, f = idx & 31;
                float v = S.cb[f];
                const float* wf = &S.ws[f * 2 * NKW];
#pragma unroll
                for (int cc = 0; cc < 2; cc++)
#pragma unroll
                    for (int k = 0; k < NKW; k++)
                        v = fmaf(S.al[cc][t + k], wf[cc * NKW + k], v);
                unsigned short h, l;
                split_bf16(v, h, l);
                S.Ahi[t * ASTR + f] = h;
                S.Alo[t * ASTR + f] = l;
            }
            const uint4* shp = g_Wlhi4;
            const uint4* slp = g_Wllo4;
#pragma unroll
            for (int u = 0; u < 2; u++) {
                int i = tid + u * 256;
                int a = i >> 2, gg = i & 3;
                int off = a * ASTR + gg * 8;
                *(uint4*)&S.Bhi[off] = shp[i];
                *(uint4*)&S.Blo[off] = slp[i];
            }
        }
        __syncthreads();

        // Two K16 steps per chunk; ldmatrix fragment loads.
#pragma unroll
        for (int ks = 0; ks < 2; ks++) {
            const int k0 = ks * 16;

            uint32_t bh[8], blr[8];
            {
                uint32_t ab = uBhi + (uint32_t)((bRow * ASTR + k0 + bColX) * 2);
                ldsm4(bh,     ab);
                ldsm4(bh + 4, ab + 16 * ASTR * 2);
                uint32_t ab2 = uBlo + (uint32_t)((bRow * ASTR + k0 + bColX) * 2);
                ldsm4(blr,     ab2);
                ldsm4(blr + 4, ab2 + 16 * ASTR * 2);
            }
#pragma unroll
            for (int mi = 0; mi < 4; mi++) {
                uint32_t aoff = (uint32_t)(((aRow + mi * 16) * ASTR + k0 + aColX) * 2);
                uint32_t ah[4], alr[4];
                ldsm4(ah,  uAhi + aoff);
                ldsm4(alr, uAlo + aoff);
#pragma unroll
                for (int ni = 0; ni < 4; ni++) {
                    mma16816(acc[mi][ni], ah,  &bh[ni * 2]);
                    mma16816(acc[mi][ni], ah,  &blr[ni * 2]);
                    mma16816(acc[mi][ni], alr, &bh[ni * 2]);
                }
            }
        }
    }

    // Epilogue: tanh + v-dot, reduce over tg lanes, then 2-stage over wn warps
    float s0[4], s1[4];
#pragma unroll
    for (int mi = 0; mi < 4; mi++) {
        float p0 = 0.f, p1 = 0.f;
#pragma unroll
        for (int ni = 0; ni < 4; ni++) {
#pragma unroll
            for (int j = 0; j < 2; j++) {
                int cdx = wn * 32 + ni * 8 + tg * 2 + j;
                p0 = fmaf(S.vw[cdx], tanhf(acc[mi][ni][j]     + S.pqc[cdx]), p0);
                p1 = fmaf(S.vw[cdx], tanhf(acc[mi][ni][2 + j] + S.pqc[cdx]), p1);
            }
        }
        p0 += __shfl_xor_sync(0xffffffffu, p0, 1);
        p0 += __shfl_xor_sync(0xffffffffu, p0, 2);
        p1 += __shfl_xor_sync(0xffffffffu, p1, 1);
        p1 += __shfl_xor_sync(0xffffffffu, p1, 2);
        s0[mi] = p0;
        s1[mi] = p1;
    }
    __syncthreads();
    if (wn < 2 && tg == 0) {
#pragma unroll
        for (int mi = 0; mi < 4; mi++) {
            int r = wm * 64 + mi * 16 + g;
            S.part[wn][r]     = s0[mi];
            S.part[wn][r + 8] = s1[mi];
        }
    }
    __syncthreads();
    if (wn >= 2 && tg == 0) {
#pragma unroll
        for (int mi = 0; mi < 4; mi++) {
            int r = wm * 64 + mi * 16 + g;
            S.part[wn - 2][r]     += s0[mi];
            S.part[wn - 2][r + 8] += s1[mi];
        }
    }
    __syncthreads();

    if (tid < TILE_T) {
        float sc = S.part[0][tid] + S.part[1][tid] + v_b[0];
        if (mask[(size_t)b * NT + t0 + tid]) sc = -CUDART_INF_F;
        g_score[(size_t)b * NT + t0 + tid] = sc;
    }
}

// ---------------------------------------------------------------------------
// Kernel 3: row softmax over T -> alignment (float4, 1024 threads)
// ---------------------------------------------------------------------------
__global__ void softmax_kernel(float* __restrict__ align_out) {
    int b = blockIdx.x;
    int tid = threadIdx.x;      // 0..1023
    __shared__ float red[1024];

    const float4* row = (const float4*)&g_score[(size_t)b * NT];
    float4 v = row[tid];
    float m = fmaxf(fmaxf(v.x, v.y), fmaxf(v.z, v.w));
    red[tid] = m;
    __syncthreads();
    for (int s = 512; s > 0; s >>= 1) {
        if (tid < s) red[tid] = fmaxf(red[tid], red[tid + s]);
        __syncthreads();
    }
    m = red[0];
    __syncthreads();

    float4 e;
    e.x = expf(v.x - m);
    e.y = expf(v.y - m);
    e.z = expf(v.z - m);
    e.w = expf(v.w - m);
    red[tid] = e.x + e.y + e.z + e.w;
    __syncthreads();
    for (int s = 512; s > 0; s >>= 1) {
        if (tid < s) red[tid] += red[tid + s];
        __syncthreads();
    }
    float inv = 1.0f / red[0];
    e.x *= inv; e.y *= inv; e.z *= inv; e.w *= inv;
    ((float4*)&align_out[(size_t)b * NT])[tid] = e;
}

// ---------------------------------------------------------------------------
// Kernel 4: context
// ---------------------------------------------------------------------------
__global__ void ctx_init_kernel(float* __restrict__ ctx) {
    ctx[blockIdx.x * NMD + threadIdx.x] = 0.f;
}

#define TCH 256
__global__ void context_kernel(const float* __restrict__ memory,
                               const float* __restrict__ align,
                               float* __restrict__ ctx) {
    int b  = blockIdx.y;
    int tc = blockIdx.x;
    int m  = threadIdx.x;   // 0..511

    __shared__ float al[TCH];
    if (threadIdx.x < TCH)
        al[threadIdx.x] = align[(size_t)b * NT + tc * TCH + threadIdx.x];
    __syncthreads();

    const float* mb = memory + (size_t)b * NT * NMD + (size_t)tc * TCH * NMD;
    float acc = 0.f;
#pragma unroll 8
    for (int t = 0; t < TCH; t++)
        acc = fmaf(al[t], mb[(size_t)t * NMD + m], acc);
    atomicAdd(&ctx[b * NMD + m], acc);
}

// ---------------------------------------------------------------------------
// kernel_launch
// ---------------------------------------------------------------------------
extern "C" void kernel_launch(void* const* d_in, const int* in_sizes, int n_in,
                              void* d_out, int out_size) {
    const float* query      = (const float*)d_in[0];
    const float* memory     = (const float*)d_in[1];
    const float* alignments = (const float*)d_in[2];
    const unsigned char* mask = (const unsigned char*)d_in[3];
    const float* Wq     = (const float*)d_in[4];
    const float* bq     = (const float*)d_in[5];
    const float* Wm     = (const float*)d_in[6];
    const float* bm     = (const float*)d_in[7];
    const float* conv_w = (const float*)d_in[8];
    const float* conv_b = (const float*)d_in[9];
    const float* Wl     = (const float*)d_in[10];
    const float* bl     = (const float*)d_in[11];
    const float* v_w    = (const float*)d_in[12];
    const float* v_b    = (const float*)d_in[13];

    float* out       = (float*)d_out;
    float* out_ctx   = out;                // [NB, NMD]
    float* out_align = out + NB * NMD;     // [NB, NT]

    static bool attr_set = false;
    if (!attr_set) {
        cudaFuncSetAttribute(score_kernel,
                             cudaFuncAttributeMaxDynamicSharedMemorySize,
                             (int)sizeof(ScoreSmem));
        attr_set = true;
    }

    ctx_init_kernel<<<NB, NMD>>>(out_ctx);
    prep_kernel<<<(NMD * NAD + TILE_T * KCH + 255) / 256, 256>>>(Wm, Wl);
    pq_kernel<<<NB, 256>>>(query, Wq, bq);
    score_kernel<<<dim3(NT / TILE_T, NB), 256, sizeof(ScoreSmem)>>>(
        memory, alignments, mask, bm, conv_w, conv_b, bl, v_w, v_b);
    softmax_kernel<<<NB, 1024>>>(out_align);
    context_kernel<<<dim3(NT / TCH, NB), 512>>>(memory, out_align, out_ctx);
}

// round 7
// speedup vs baseline: 2.6456x; 1.0286x over previous
#include <cuda_runtime.h>
#include <cuda_bf16.h>
#include <math.h>
#include <math_constants.h>
#include <stdint.h>

// Problem constants
#define NB   32
#define NT   4096
#define NQD  1024
#define NMD  512
#define NAD  128
#define NF   32
#define NKW  31
#define NPAD 15

// Score-kernel tiling
#define TILE_T  128
#define KCH     32          // K per chunk; loc chunk (Wl, K=32) is chunk 16
#define NCHUNK  16
#define ASTR    40          // padded row stride in elems (80 B, 16B-multiple)

// ---------------------------------------------------------------------------
// Device scratch (no allocation allowed). uint4-typed => 16B alignment.
// ---------------------------------------------------------------------------
__device__ alignas(16) float g_pq[NB * NAD];
__device__ alignas(16) float g_score[NB * NT];
// Pre-split B operands: [chunk][a(128)][k(32)] bf16 packed as uint4 (8 shorts)
__device__ uint4 g_Bhi4[NCHUNK * TILE_T * KCH / 8];
__device__ uint4 g_Blo4[NCHUNK * TILE_T * KCH / 8];
__device__ uint4 g_Wlhi4[TILE_T * KCH / 8];
__device__ uint4 g_Wllo4[TILE_T * KCH / 8];

// ---------------------------------------------------------------------------
// Shared-memory layout: compiler-verified struct over dynamic smem.
// B tiles double-buffered for cp.async pipelining.
// ---------------------------------------------------------------------------
struct ScoreSmem {
    alignas(16) unsigned short Ahi[TILE_T * ASTR];
    alignas(16) unsigned short Alo[TILE_T * ASTR];
    alignas(16) unsigned short Bhi[2][TILE_T * ASTR];
    alignas(16) unsigned short Blo[2][TILE_T * ASTR];
    float pqc[NAD];
    float vw[NAD];
    float al[2][TILE_T + NKW - 1];
    float ws[NF * 2 * NKW];     // 1984 floats
    float cb[NF];
    float part[2][TILE_T];
};
static_assert(sizeof(ScoreSmem) <= 100 * 1024, "smem overflow");

// ---------------------------------------------------------------------------
// Helpers
// ---------------------------------------------------------------------------
__device__ __forceinline__ uint32_t smem_u32(const void* p) {
    uint32_t r;
    asm("{ .reg .u64 t; cvta.to.shared.u64 t, %1; cvt.u32.u64 %0, t; }"
        : "=r"(r) : "l"(p));
    return r;
}

__device__ __forceinline__ void ldsm4(uint32_t* r, uint32_t addr) {
    asm volatile("ldmatrix.sync.aligned.m8n8.x4.shared.b16 {%0,%1,%2,%3}, [%4];"
                 : "=r"(r[0]), "=r"(r[1]), "=r"(r[2]), "=r"(r[3]) : "r"(addr));
}

__device__ __forceinline__ void mma16816(float* c, const uint32_t* a,
                                         const uint32_t* b) {
    asm volatile(
        "mma.sync.aligned.m16n8k16.row.col.f32.bf16.bf16.f32 "
        "{%0,%1,%2,%3}, {%4,%5,%6,%7}, {%8,%9}, {%0,%1,%2,%3};"
        : "+f"(c[0]), "+f"(c[1]), "+f"(c[2]), "+f"(c[3])
        : "r"(a[0]), "r"(a[1]), "r"(a[2]), "r"(a[3]), "r"(b[0]), "r"(b[1]));
}

#define CP_ASYNC16(dst_u32, src_ptr) \
    asm volatile("cp.async.cg.shared.global [%0], [%1], 16;" \
                 :: "r"(dst_u32), "l"(src_ptr))
#define CP_COMMIT() asm volatile("cp.async.commit_group;")
#define CP_WAIT1()  asm volatile("cp.async.wait_group 1;")
#define CP_WAIT0()  asm volatile("cp.async.wait_group 0;")

__device__ __forceinline__ void split_bf16(float x, unsigned short& h,
                                           unsigned short& l) {
    __nv_bfloat16 hb = __float2bfloat16(x);
    float hf = __bfloat162float(hb);
    __nv_bfloat16 lb = __float2bfloat16(x - hf);
    h = ((__nv_bfloat16_raw)hb).x;
    l = ((__nv_bfloat16_raw)lb).x;
}

// ---------------------------------------------------------------------------
// Prep: split Wm / Wl into bf16 hi/lo, [chunk][a][k] linear layout
// ---------------------------------------------------------------------------
__global__ void prep_kernel(const float* __restrict__ Wm,
                            const float* __restrict__ Wl) {
    int idx = blockIdx.x * blockDim.x + threadIdx.x;
    unsigned short* bhi = (unsigned short*)g_Bhi4;
    unsigned short* blo = (unsigned short*)g_Blo4;
    unsigned short* whi = (unsigned short*)g_Wlhi4;
    unsigned short* wlo = (unsigned short*)g_Wllo4;
    if (idx < NMD * NAD) {
        int k = idx >> 7, a = idx & 127;
        int c = k >> 5, kk = k & 31;
        unsigned short h, l;
        split_bf16(Wm[k * NAD + a], h, l);
        int dst = c * (TILE_T * KCH) + a * KCH + kk;
        bhi[dst] = h;
        blo[dst] = l;
    } else if (idx < NMD * NAD + TILE_T * KCH) {
        int r = idx - NMD * NAD;
        int a = r >> 5, kk = r & 31;
        unsigned short h, l;
        split_bf16(Wl[kk * NAD + a], h, l);   // kk < 32 == NF
        whi[a * KCH + kk] = h;
        wlo[a * KCH + kk] = l;
    }
}

// ---------------------------------------------------------------------------
// Kernel 1: processed query (split-K over 2 thread groups)
// ---------------------------------------------------------------------------
__global__ void pq_kernel(const float* __restrict__ query,
                          const float* __restrict__ Wq,
                          const float* __restrict__ bq) {
    __shared__ float qs[NQD];
    __shared__ float partial[256];
    int b = blockIdx.x;
    int tid = threadIdx.x;
    for (int i = tid; i < NQD; i += 256)
        qs[i] = query[b * NQD + i];
    __syncthreads();
    int a = tid & 127;
    int h = tid >> 7;
    float acc = 0.f;
    int q0 = h * (NQD / 2);
#pragma unroll 8
    for (int q = 0; q < NQD / 2; q++)
        acc = fmaf(qs[q0 + q], Wq[(q0 + q) * NAD + a], acc);
    partial[tid] = acc;
    __syncthreads();
    if (tid < 128)
        g_pq[b * NAD + a] = bq[a] + partial[tid] + partial[tid + 128];
}

// ---------------------------------------------------------------------------
// Kernel 2: fused score kernel. Pipelined: cp.async double-buffered B,
// register-prefetched A, single-buffered A tiles, ldmatrix + mma.sync bf16.
// ---------------------------------------------------------------------------
__global__ __launch_bounds__(256, 2)
void score_kernel(const float* __restrict__ memory,
                  const float* __restrict__ alignments,
                  const unsigned char* __restrict__ mask,
                  const float* __restrict__ bm,
                  const float* __restrict__ conv_w,
                  const float* __restrict__ conv_b,
                  const float* __restrict__ bl,
                  const float* __restrict__ v_w,
                  const float* __restrict__ v_b) {
    extern __shared__ char smem_raw[];
    ScoreSmem& S = *reinterpret_cast<ScoreSmem*>(smem_raw);

    const int tid  = threadIdx.x;
    const int lane = tid & 31;
    const int wid  = tid >> 5;
    const int wm   = wid >> 2;
    const int wn   = wid & 3;
    const int g    = lane >> 2;
    const int tg   = lane & 3;
    const int b    = blockIdx.y;
    const int t0   = blockIdx.x * TILE_T;

    // Per-thread A/B staging geometry (two units of 8 elems each)
    const int tA = tid >> 2;              // row 0..63 (unit 0) / +64 (unit 1)
    const int gA = tid & 3;               // 8-elem group 0..3

    for (int i = tid; i < NF * 2 * NKW; i += 256) S.ws[i] = conv_w[i];
    for (int i = tid; i < 2 * (TILE_T + NKW - 1); i += 256) {
        int c = i / (TILE_T + NKW - 1);
        int p = i % (TILE_T + NKW - 1);
        int t = t0 - NPAD + p;
        S.al[c][p] = (t >= 0 && t < NT)
                   ? alignments[((size_t)b * NT + t) * 2 + c] : 0.f;
    }
    if (tid < NAD) {
        S.pqc[tid] = g_pq[b * NAD + tid] + bm[tid] + bl[tid];
        S.vw[tid]  = v_w[tid];
    }
    if (tid < NF) S.cb[tid] = conv_b[tid];

    const float* memb = memory + ((size_t)b * NT + t0) * NMD;

    const uint32_t uAhi = smem_u32(S.Ahi);
    const uint32_t uAlo = smem_u32(S.Alo);
    const uint32_t uBhi[2] = {smem_u32(S.Bhi[0]), smem_u32(S.Bhi[1])};
    const uint32_t uBlo[2] = {smem_u32(S.Blo[0]), smem_u32(S.Blo[1])};

    // cp.async destination offsets for this thread's two B units
    const int iB0 = tid, iB1 = tid + 256;
    const uint32_t offB0 = (uint32_t)(((iB0 >> 2) * ASTR + (iB0 & 3) * 8) * 2);
    const uint32_t offB1 = (uint32_t)(((iB1 >> 2) * ASTR + (iB1 & 3) * 8) * 2);

    float acc[4][4][4];
#pragma unroll
    for (int mi = 0; mi < 4; mi++)
#pragma unroll
        for (int ni = 0; ni < 4; ni++)
#pragma unroll
            for (int j = 0; j < 4; j++) acc[mi][ni][j] = 0.f;

    // ldmatrix per-lane addressing
    const int aRow  = wm * 64 + (lane & 15);
    const int aColX = (lane >> 4) * 8;
    const int bRow  = wn * 32 + ((lane >> 4) << 3) + (lane & 7);
    const int bColX = ((lane >> 3) & 1) * 8;

    // ---- Prologue: prefetch chunk 0 (B via cp.async, A via registers) ----
    {
        const uint4* shp = g_Bhi4;
        const uint4* slp = g_Blo4;
        CP_ASYNC16(uBhi[0] + offB0, shp + iB0);
        CP_ASYNC16(uBhi[0] + offB1, shp + iB1);
        CP_ASYNC16(uBlo[0] + offB0, slp + iB0);
        CP_ASYNC16(uBlo[0] + offB1, slp + iB1);
        CP_COMMIT();
    }
    float4 a4[2][2];
#pragma unroll
    for (int u = 0; u < 2; u++) {
        const float* src = memb + (size_t)(tA + u * 64) * NMD + gA * 8;
        a4[u][0] = *(const float4*)src;
        a4[u][1] = *(const float4*)(src + 4);
    }

    for (int c = 0; c <= NCHUNK; c++) {
        __syncthreads();   // MMAs of chunk c-1 done reading A/B tiles

        if (c < NCHUNK) {
            // Convert prefetched A registers -> bf16 hi/lo, store to smem
#pragma unroll
            for (int u = 0; u < 2; u++) {
                float f[8] = {a4[u][0].x, a4[u][0].y, a4[u][0].z, a4[u][0].w,
                              a4[u][1].x, a4[u][1].y, a4[u][1].z, a4[u][1].w};
                uint32_t hw[4], lw[4];
#pragma unroll
                for (int j = 0; j < 4; j++) {
                    unsigned short h0, l0, h1, l1;
                    split_bf16(f[2 * j],     h0, l0);
                    split_bf16(f[2 * j + 1], h1, l1);
                    hw[j] = (uint32_t)h0 | ((uint32_t)h1 << 16);
                    lw[j] = (uint32_t)l0 | ((uint32_t)l1 << 16);
                }
                int off = (tA + u * 64) * ASTR + gA * 8;
                *(uint4*)&S.Ahi[off] = make_uint4(hw[0], hw[1], hw[2], hw[3]);
                *(uint4*)&S.Alo[off] = make_uint4(lw[0], lw[1], lw[2], lw[3]);
            }
        } else {
            // loc chunk: conv -> bf16 hi/lo (K = 32)
            for (int idx = tid; idx < TILE_T * NF; idx += 256) {
                int t = idx >> 5, f = idx & 31;
                float v = S.cb[f];
                const float* wf = &S.ws[f * 2 * NKW];
#pragma unroll
                for (int cc = 0; cc < 2; cc++)
#pragma unroll
                    for (int k = 0; k < NKW; k++)
                        v = fmaf(S.al[cc][t + k], wf[cc * NKW + k], v);
                unsigned short h, l;
                split_bf16(v, h, l);
                S.Ahi[t * ASTR + f] = h;
                S.Alo[t * ASTR + f] = l;
            }
        }

        // Prefetch chunk c+1 (B via cp.async into other buffer; A into regs)
        if (c < NCHUNK) {
            const int nc = c + 1;
            const int nb = nc & 1;
            const uint4* shp = (nc < NCHUNK) ? (g_Bhi4 + nc * 512) : g_Wlhi4;
            const uint4* slp = (nc < NCHUNK) ? (g_Blo4 + nc * 512) : g_Wllo4;
            CP_ASYNC16(uBhi[nb] + offB0, shp + iB0);
            CP_ASYNC16(uBhi[nb] + offB1, shp + iB1);
            CP_ASYNC16(uBlo[nb] + offB0, slp + iB0);
            CP_ASYNC16(uBlo[nb] + offB1, slp + iB1);
            CP_COMMIT();
            if (nc < NCHUNK) {
#pragma unroll
                for (int u = 0; u < 2; u++) {
                    const float* src =
                        memb + (size_t)(tA + u * 64) * NMD + nc * KCH + gA * 8;
                    a4[u][0] = *(const float4*)src;
                    a4[u][1] = *(const float4*)(src + 4);
                }
            }
            CP_WAIT1();     // chunk c's B group complete
        } else {
            CP_WAIT0();
        }
        __syncthreads();

        // Two K16 steps; ldmatrix fragment loads; 3-product hi/lo MMAs
        const uint32_t uBh = uBhi[c & 1];
        const uint32_t uBl = uBlo[c & 1];
#pragma unroll
        for (int ks = 0; ks < 2; ks++) {
            const int k0 = ks * 16;

            uint32_t bh[8], blr[8];
            {
                uint32_t ab = uBh + (uint32_t)((bRow * ASTR + k0 + bColX) * 2);
                ldsm4(bh,     ab);
                ldsm4(bh + 4, ab + 16 * ASTR * 2);
                uint32_t ab2 = uBl + (uint32_t)((bRow * ASTR + k0 + bColX) * 2);
                ldsm4(blr,     ab2);
                ldsm4(blr + 4, ab2 + 16 * ASTR * 2);
            }
#pragma unroll
            for (int mi = 0; mi < 4; mi++) {
                uint32_t aoff =
                    (uint32_t)(((aRow + mi * 16) * ASTR + k0 + aColX) * 2);
                uint32_t ah[4], alr[4];
                ldsm4(ah,  uAhi + aoff);
                ldsm4(alr, uAlo + aoff);
#pragma unroll
                for (int ni = 0; ni < 4; ni++) {
                    mma16816(acc[mi][ni], ah,  &bh[ni * 2]);
                    mma16816(acc[mi][ni], ah,  &blr[ni * 2]);
                    mma16816(acc[mi][ni], alr, &bh[ni * 2]);
                }
            }
        }
    }

    // Epilogue: tanh + v-dot, reduce over tg lanes, then 2-stage over wn warps
    float s0[4], s1[4];
#pragma unroll
    for (int mi = 0; mi < 4; mi++) {
        float p0 = 0.f, p1 = 0.f;
#pragma unroll
        for (int ni = 0; ni < 4; ni++) {
#pragma unroll
            for (int j = 0; j < 2; j++) {
                int cdx = wn * 32 + ni * 8 + tg * 2 + j;
                p0 = fmaf(S.vw[cdx], tanhf(acc[mi][ni][j]     + S.pqc[cdx]), p0);
                p1 = fmaf(S.vw[cdx], tanhf(acc[mi][ni][2 + j] + S.pqc[cdx]), p1);
            }
        }
        p0 += __shfl_xor_sync(0xffffffffu, p0, 1);
        p0 += __shfl_xor_sync(0xffffffffu, p0, 2);
        p1 += __shfl_xor_sync(0xffffffffu, p1, 1);
        p1 += __shfl_xor_sync(0xffffffffu, p1, 2);
        s0[mi] = p0;
        s1[mi] = p1;
    }
    __syncthreads();
    if (wn < 2 && tg == 0) {
#pragma unroll
        for (int mi = 0; mi < 4; mi++) {
            int r = wm * 64 + mi * 16 + g;
            S.part[wn][r]     = s0[mi];
            S.part[wn][r + 8] = s1[mi];
        }
    }
    __syncthreads();
    if (wn >= 2 && tg == 0) {
#pragma unroll
        for (int mi = 0; mi < 4; mi++) {
            int r = wm * 64 + mi * 16 + g;
            S.part[wn - 2][r]     += s0[mi];
            S.part[wn - 2][r + 8] += s1[mi];
        }
    }
    __syncthreads();

    if (tid < TILE_T) {
        float sc = S.part[0][tid] + S.part[1][tid] + v_b[0];
        if (mask[(size_t)b * NT + t0 + tid]) sc = -CUDART_INF_F;
        g_score[(size_t)b * NT + t0 + tid] = sc;
    }
}

// ---------------------------------------------------------------------------
// Kernel 3: row softmax over T -> alignment (float4, 1024 threads)
// ---------------------------------------------------------------------------
__global__ void softmax_kernel(float* __restrict__ align_out) {
    int b = blockIdx.x;
    int tid = threadIdx.x;
    __shared__ float red[1024];

    const float4* row = (const float4*)&g_score[(size_t)b * NT];
    float4 v = row[tid];
    float m = fmaxf(fmaxf(v.x, v.y), fmaxf(v.z, v.w));
    red[tid] = m;
    __syncthreads();
    for (int s = 512; s > 0; s >>= 1) {
        if (tid < s) red[tid] = fmaxf(red[tid], red[tid + s]);
        __syncthreads();
    }
    m = red[0];
    __syncthreads();

    float4 e;
    e.x = expf(v.x - m);
    e.y = expf(v.y - m);
    e.z = expf(v.z - m);
    e.w = expf(v.w - m);
    red[tid] = e.x + e.y + e.z + e.w;
    __syncthreads();
    for (int s = 512; s > 0; s >>= 1) {
        if (tid < s) red[tid] += red[tid + s];
        __syncthreads();
    }
    float inv = 1.0f / red[0];
    e.x *= inv; e.y *= inv; e.z *= inv; e.w *= inv;
    ((float4*)&align_out[(size_t)b * NT])[tid] = e;
}

// ---------------------------------------------------------------------------
// Kernel 4: context
// ---------------------------------------------------------------------------
__global__ void ctx_init_kernel(float* __restrict__ ctx) {
    ctx[blockIdx.x * NMD + threadIdx.x] = 0.f;
}

#define TCH 256
__global__ void context_kernel(const float* __restrict__ memory,
                               const float* __restrict__ align,
                               float* __restrict__ ctx) {
    int b  = blockIdx.y;
    int tc = blockIdx.x;
    int m  = threadIdx.x;

    __shared__ float al[TCH];
    if (threadIdx.x < TCH)
        al[threadIdx.x] = align[(size_t)b * NT + tc * TCH + threadIdx.x];
    __syncthreads();

    const float* mb = memory + (size_t)b * NT * NMD + (size_t)tc * TCH * NMD;
    float acc = 0.f;
#pragma unroll 8
    for (int t = 0; t < TCH; t++)
        acc = fmaf(al[t], mb[(size_t)t * NMD + m], acc);
    atomicAdd(&ctx[b * NMD + m], acc);
}

// ---------------------------------------------------------------------------
// kernel_launch
// ---------------------------------------------------------------------------
extern "C" void kernel_launch(void* const* d_in, const int* in_sizes, int n_in,
                              void* d_out, int out_size) {
    const float* query      = (const float*)d_in[0];
    const float* memory     = (const float*)d_in[1];
    const float* alignments = (const float*)d_in[2];
    const unsigned char* mask = (const unsigned char*)d_in[3];
    const float* Wq     = (const float*)d_in[4];
    const float* bq     = (const float*)d_in[5];
    const float* Wm     = (const float*)d_in[6];
    const float* bm     = (const float*)d_in[7];
    const float* conv_w = (const float*)d_in[8];
    const float* conv_b = (const float*)d_in[9];
    const float* Wl     = (const float*)d_in[10];
    const float* bl     = (const float*)d_in[11];
    const float* v_w    = (const float*)d_in[12];
    const float* v_b    = (const float*)d_in[13];

    float* out       = (float*)d_out;
    float* out_ctx   = out;                // [NB, NMD]
    float* out_align = out + NB * NMD;     // [NB, NT]

    static bool attr_set = false;
    if (!attr_set) {
        cudaFuncSetAttribute(score_kernel,
                             cudaFuncAttributeMaxDynamicSharedMemorySize,
                             (int)sizeof(ScoreSmem));
        attr_set = true;
    }

    ctx_init_kernel<<<NB, NMD>>>(out_ctx);
    prep_kernel<<<(NMD * NAD + TILE_T * KCH + 255) / 256, 256>>>(Wm, Wl);
    pq_kernel<<<NB, 256>>>(query, Wq, bq);
    score_kernel<<<dim3(NT / TILE_T, NB), 256, sizeof(ScoreSmem)>>>(
        memory, alignments, mask, bm, conv_w, conv_b, bl, v_w, v_b);
    softmax_kernel<<<NB, 1024>>>(out_align);
    context_kernel<<<dim3(NT / TCH, NB), 512>>>(memory, out_align, out_ctx);
}

// round 9
// speedup vs baseline: 2.6992x; 1.0202x over previous
#include <cuda_runtime.h>
#include <cuda_bf16.h>
#include <math.h>
#include <math_constants.h>
#include <stdint.h>

// Problem constants
#define NB   32
#define NT   4096
#define NQD  1024
#define NMD  512
#define NAD  128
#define NF   32
#define NKW  31
#define NPAD 15

// Score-kernel tiling
#define TILE_T  128
#define KCH     32          // K per chunk; loc chunk (Wl, K=32) is chunk 16
#define NCHUNK  16
#define ASTR    40          // padded row stride in elems (80 B, 16B-multiple)

// ---------------------------------------------------------------------------
// Device scratch (no allocation allowed). uint4-typed => 16B alignment.
// ---------------------------------------------------------------------------
__device__ alignas(16) float g_pq[NB * NAD];
__device__ alignas(16) float g_score[NB * NT];
// Pre-split B operands: [chunk][a(128)][k(32)] bf16 packed as uint4 (8 shorts)
__device__ uint4 g_Bhi4[NCHUNK * TILE_T * KCH / 8];
__device__ uint4 g_Blo4[NCHUNK * TILE_T * KCH / 8];
__device__ uint4 g_Wlhi4[TILE_T * KCH / 8];
__device__ uint4 g_Wllo4[TILE_T * KCH / 8];

// ---------------------------------------------------------------------------
// Shared memory: compiler-verified struct; A and B tiles double-buffered.
// ---------------------------------------------------------------------------
struct ScoreSmem {
    alignas(16) unsigned short Ahi[2][TILE_T * ASTR];
    alignas(16) unsigned short Alo[2][TILE_T * ASTR];
    alignas(16) unsigned short Bhi[2][TILE_T * ASTR];
    alignas(16) unsigned short Blo[2][TILE_T * ASTR];
    float pqc[NAD];
    float vw[NAD];
    float al[2][TILE_T + NKW - 1];
    float ws[NF * 2 * NKW];     // 1984 floats
    float cb[NF];
    float part[2][TILE_T];
};
static_assert(sizeof(ScoreSmem) <= 110 * 1024, "smem overflow");

// ---------------------------------------------------------------------------
// Helpers
// ---------------------------------------------------------------------------
__device__ __forceinline__ uint32_t smem_u32(const void* p) {
    uint32_t r;
    asm("{ .reg .u64 t; cvta.to.shared.u64 t, %1; cvt.u32.u64 %0, t; }"
        : "=r"(r) : "l"(p));
    return r;
}

__device__ __forceinline__ void ldsm4(uint32_t* r, uint32_t addr) {
    asm volatile("ldmatrix.sync.aligned.m8n8.x4.shared.b16 {%0,%1,%2,%3}, [%4];"
                 : "=r"(r[0]), "=r"(r[1]), "=r"(r[2]), "=r"(r[3]) : "r"(addr));
}

__device__ __forceinline__ void mma16816(float* c, const uint32_t* a,
                                         const uint32_t* b) {
    asm volatile(
        "mma.sync.aligned.m16n8k16.row.col.f32.bf16.bf16.f32 "
        "{%0,%1,%2,%3}, {%4,%5,%6,%7}, {%8,%9}, {%0,%1,%2,%3};"
        : "+f"(c[0]), "+f"(c[1]), "+f"(c[2]), "+f"(c[3])
        : "r"(a[0]), "r"(a[1]), "r"(a[2]), "r"(a[3]), "r"(b[0]), "r"(b[1]));
}

#define CP_ASYNC16(dst_u32, src_ptr) \
    asm volatile("cp.async.cg.shared.global [%0], [%1], 16;" \
                 :: "r"(dst_u32), "l"(src_ptr))
#define CP_COMMIT() asm volatile("cp.async.commit_group;")
#define CP_WAIT0()  asm volatile("cp.async.wait_group 0;")

__device__ __forceinline__ void split_bf16(float x, unsigned short& h,
                                           unsigned short& l) {
    __nv_bfloat16 hb = __float2bfloat16(x);
    float hf = __bfloat162float(hb);
    __nv_bfloat16 lb = __float2bfloat16(x - hf);
    h = ((__nv_bfloat16_raw)hb).x;
    l = ((__nv_bfloat16_raw)lb).x;
}

// ---------------------------------------------------------------------------
// Prep: split Wm / Wl into bf16 hi/lo, [chunk][a][k] linear layout
// ---------------------------------------------------------------------------
__global__ void prep_kernel(const float* __restrict__ Wm,
                            const float* __restrict__ Wl) {
    int idx = blockIdx.x * blockDim.x + threadIdx.x;
    unsigned short* bhi = (unsigned short*)g_Bhi4;
    unsigned short* blo = (unsigned short*)g_Blo4;
    unsigned short* whi = (unsigned short*)g_Wlhi4;
    unsigned short* wlo = (unsigned short*)g_Wllo4;
    if (idx < NMD * NAD) {
        int k = idx >> 7, a = idx & 127;
        int c = k >> 5, kk = k & 31;
        unsigned short h, l;
        split_bf16(Wm[k * NAD + a], h, l);
        int dst = c * (TILE_T * KCH) + a * KCH + kk;
        bhi[dst] = h;
        blo[dst] = l;
    } else if (idx < NMD * NAD + TILE_T * KCH) {
        int r = idx - NMD * NAD;
        int a = r >> 5, kk = r & 31;
        unsigned short h, l;
        split_bf16(Wl[kk * NAD + a], h, l);   // kk < 32 == NF
        whi[a * KCH + kk] = h;
        wlo[a * KCH + kk] = l;
    }
}

// ---------------------------------------------------------------------------
// Kernel 1: processed query (split-K over 2 thread groups)
// ---------------------------------------------------------------------------
__global__ void pq_kernel(const float* __restrict__ query,
                          const float* __restrict__ Wq,
                          const float* __restrict__ bq) {
    __shared__ float qs[NQD];
    __shared__ float partial[256];
    int b = blockIdx.x;
    int tid = threadIdx.x;
    for (int i = tid; i < NQD; i += 256)
        qs[i] = query[b * NQD + i];
    __syncthreads();
    int a = tid & 127;
    int h = tid >> 7;
    float acc = 0.f;
    int q0 = h * (NQD / 2);
#pragma unroll 8
    for (int q = 0; q < NQD / 2; q++)
        acc = fmaf(qs[q0 + q], Wq[(q0 + q) * NAD + a], acc);
    partial[tid] = acc;
    __syncthreads();
    if (tid < 128)
        g_pq[b * NAD + a] = bq[a] + partial[tid] + partial[tid + 128];
}

// ---------------------------------------------------------------------------
// Kernel 2: fused score kernel. Fully double-buffered (A and B), ONE barrier
// per chunk; B staged via cp.async AFTER the barrier (race-free ordering):
//   wait B(c) -> barrier -> stage B(c+1) -> convert A(c+1) -> MMA(c)
// ---------------------------------------------------------------------------
__global__ __launch_bounds__(256, 2)
void score_kernel(const float* __restrict__ memory,
                  const float* __restrict__ alignments,
                  const unsigned char* __restrict__ mask,
                  const float* __restrict__ bm,
                  const float* __restrict__ conv_w,
                  const float* __restrict__ conv_b,
                  const float* __restrict__ bl,
                  const float* __restrict__ v_w,
                  const float* __restrict__ v_b) {
    extern __shared__ char smem_raw[];
    ScoreSmem& S = *reinterpret_cast<ScoreSmem*>(smem_raw);

    const int tid  = threadIdx.x;
    const int lane = tid & 31;
    const int wid  = tid >> 5;
    const int wm   = wid >> 2;
    const int wn   = wid & 3;
    const int g    = lane >> 2;
    const int tg   = lane & 3;
    const int b    = blockIdx.y;
    const int t0   = blockIdx.x * TILE_T;

    // Per-thread A staging geometry (two units of 8 elems each)
    const int tA = tid >> 2;              // row 0..63 (unit0) / +64 (unit1)
    const int gA = tid & 3;               // 8-elem group

    for (int i = tid; i < NF * 2 * NKW; i += 256) S.ws[i] = conv_w[i];
    for (int i = tid; i < 2 * (TILE_T + NKW - 1); i += 256) {
        int c = i / (TILE_T + NKW - 1);
        int p = i % (TILE_T + NKW - 1);
        int t = t0 - NPAD + p;
        S.al[c][p] = (t >= 0 && t < NT)
                   ? alignments[((size_t)b * NT + t) * 2 + c] : 0.f;
    }
    if (tid < NAD) {
        S.pqc[tid] = g_pq[b * NAD + tid] + bm[tid] + bl[tid];
        S.vw[tid]  = v_w[tid];
    }
    if (tid < NF) S.cb[tid] = conv_b[tid];

    const float* memb = memory + ((size_t)b * NT + t0) * NMD;

    const uint32_t uAhi[2] = {smem_u32(S.Ahi[0]), smem_u32(S.Ahi[1])};
    const uint32_t uAlo[2] = {smem_u32(S.Alo[0]), smem_u32(S.Alo[1])};
    const uint32_t uBhi[2] = {smem_u32(S.Bhi[0]), smem_u32(S.Bhi[1])};
    const uint32_t uBlo[2] = {smem_u32(S.Blo[0]), smem_u32(S.Blo[1])};

    // cp.async destination offsets for this thread's two B units
    const int iB0 = tid, iB1 = tid + 256;
    const uint32_t offB0 = (uint32_t)(((iB0 >> 2) * ASTR + (iB0 & 3) * 8) * 2);
    const uint32_t offB1 = (uint32_t)(((iB1 >> 2) * ASTR + (iB1 & 3) * 8) * 2);

    float acc[4][4][4];
#pragma unroll
    for (int mi = 0; mi < 4; mi++)
#pragma unroll
        for (int ni = 0; ni < 4; ni++)
#pragma unroll
            for (int j = 0; j < 4; j++) acc[mi][ni][j] = 0.f;

    // ldmatrix per-lane addressing
    const int aRow  = wm * 64 + (lane & 15);
    const int aColX = (lane >> 4) * 8;
    const int bRow  = wn * 32 + ((lane >> 4) << 3) + (lane & 7);
    const int bColX = ((lane >> 3) & 1) * 8;

    // Convert regs -> bf16 hi/lo tile in buffer `buf`
    float4 a4[2][2];
    auto convertA = [&](int buf) {
#pragma unroll
        for (int u = 0; u < 2; u++) {
            float f[8] = {a4[u][0].x, a4[u][0].y, a4[u][0].z, a4[u][0].w,
                          a4[u][1].x, a4[u][1].y, a4[u][1].z, a4[u][1].w};
            uint32_t hw[4], lw[4];
#pragma unroll
            for (int j = 0; j < 4; j++) {
                unsigned short h0, l0, h1, l1;
                split_bf16(f[2 * j],     h0, l0);
                split_bf16(f[2 * j + 1], h1, l1);
                hw[j] = (uint32_t)h0 | ((uint32_t)h1 << 16);
                lw[j] = (uint32_t)l0 | ((uint32_t)l1 << 16);
            }
            int off = (tA + u * 64) * ASTR + gA * 8;
            *(uint4*)&S.Ahi[buf][off] = make_uint4(hw[0], hw[1], hw[2], hw[3]);
            *(uint4*)&S.Alo[buf][off] = make_uint4(lw[0], lw[1], lw[2], lw[3]);
        }
    };
    auto loadA = [&](int c) {
#pragma unroll
        for (int u = 0; u < 2; u++) {
            const float* src = memb + (size_t)(tA + u * 64) * NMD + c * KCH + gA * 8;
            a4[u][0] = *(const float4*)src;
            a4[u][1] = *(const float4*)(src + 4);
        }
    };
    auto stageB = [&](int c) {   // cp.async chunk c's B into buffer c&1
        const uint4* shp = (c < NCHUNK) ? (g_Bhi4 + c * 512) : g_Wlhi4;
        const uint4* slp = (c < NCHUNK) ? (g_Blo4 + c * 512) : g_Wllo4;
        const int nb = c & 1;
        CP_ASYNC16(uBhi[nb] + offB0, shp + iB0);
        CP_ASYNC16(uBhi[nb] + offB1, shp + iB1);
        CP_ASYNC16(uBlo[nb] + offB0, slp + iB0);
        CP_ASYNC16(uBlo[nb] + offB1, slp + iB1);
        CP_COMMIT();
    };

    // ---- Prologue: stage chunk 0 completely ----
    stageB(0);
    loadA(0);
    convertA(0);       // published by the barrier inside iter 0
    loadA(1);

    for (int c = 0; c <= NCHUNK; c++) {
        const int nc = c + 1;
        // 1) own-thread wait for B(c) — the only group in flight
        CP_WAIT0();
        // 2) single barrier: publishes B(c) + A(c); fences MMA(c-1) reads
        __syncthreads();
        // 3) stage next B AFTER the barrier (prev reader MMA(c-1) fenced)
        if (nc <= NCHUNK) stageB(nc);
        // 4) convert A(c+1) into the other buffer (or loc conv for chunk 16)
        if (nc < NCHUNK) {
            convertA(nc & 1);
            if (nc + 1 < NCHUNK) loadA(nc + 1);   // prefetch A(c+2)
        } else if (nc == NCHUNK) {
            // loc chunk: conv -> bf16 hi/lo into buffer 0 (16&1==0)
            for (int idx = tid; idx < TILE_T * NF; idx += 256) {
                int t = idx >> 5, f = idx & 31;
                float v = S.cb[f];
                const float* wf = &S.ws[f * 2 * NKW];
#pragma unroll
                for (int cc = 0; cc < 2; cc++)
#pragma unroll
                    for (int k = 0; k < NKW; k++)
                        v = fmaf(S.al[cc][t + k], wf[cc * NKW + k], v);
                unsigned short h, l;
                split_bf16(v, h, l);
                S.Ahi[0][t * ASTR + f] = h;
                S.Alo[0][t * ASTR + f] = l;
            }
        }
        // 5) MMA on chunk c (buffers c&1)
        const uint32_t uAh = uAhi[c & 1], uAl = uAlo[c & 1];
        const uint32_t uBh = uBhi[c & 1], uBl = uBlo[c & 1];
#pragma unroll
        for (int ks = 0; ks < 2; ks++) {
            const int k0 = ks * 16;
            uint32_t bh[8], blr[8];
            {
                uint32_t ab = uBh + (uint32_t)((bRow * ASTR + k0 + bColX) * 2);
                ldsm4(bh,     ab);
                ldsm4(bh + 4, ab + 16 * ASTR * 2);
                uint32_t ab2 = uBl + (uint32_t)((bRow * ASTR + k0 + bColX) * 2);
                ldsm4(blr,     ab2);
                ldsm4(blr + 4, ab2 + 16 * ASTR * 2);
            }
#pragma unroll
            for (int mi = 0; mi < 4; mi++) {
                uint32_t aoff =
                    (uint32_t)(((aRow + mi * 16) * ASTR + k0 + aColX) * 2);
                uint32_t ah[4], alr[4];
                ldsm4(ah,  uAh + aoff);
                ldsm4(alr, uAl + aoff);
#pragma unroll
                for (int ni = 0; ni < 4; ni++) {
                    mma16816(acc[mi][ni], ah,  &bh[ni * 2]);
                    mma16816(acc[mi][ni], ah,  &blr[ni * 2]);
                    mma16816(acc[mi][ni], alr, &bh[ni * 2]);
                }
            }
        }
    }

    // Epilogue: tanh + v-dot, reduce over tg lanes, then 2-stage over wn warps
    float s0[4], s1[4];
#pragma unroll
    for (int mi = 0; mi < 4; mi++) {
        float p0 = 0.f, p1 = 0.f;
#pragma unroll
        for (int ni = 0; ni < 4; ni++) {
#pragma unroll
            for (int j = 0; j < 2; j++) {
                int cdx = wn * 32 + ni * 8 + tg * 2 + j;
                p0 = fmaf(S.vw[cdx], tanhf(acc[mi][ni][j]     + S.pqc[cdx]), p0);
                p1 = fmaf(S.vw[cdx], tanhf(acc[mi][ni][2 + j] + S.pqc[cdx]), p1);
            }
        }
        p0 += __shfl_xor_sync(0xffffffffu, p0, 1);
        p0 += __shfl_xor_sync(0xffffffffu, p0, 2);
        p1 += __shfl_xor_sync(0xffffffffu, p1, 1);
        p1 += __shfl_xor_sync(0xffffffffu, p1, 2);
        s0[mi] = p0;
        s1[mi] = p1;
    }
    __syncthreads();
    if (wn < 2 && tg == 0) {
#pragma unroll
        for (int mi = 0; mi < 4; mi++) {
            int r = wm * 64 + mi * 16 + g;
            S.part[wn][r]     = s0[mi];
            S.part[wn][r + 8] = s1[mi];
        }
    }
    __syncthreads();
    if (wn >= 2 && tg == 0) {
#pragma unroll
        for (int mi = 0; mi < 4; mi++) {
            int r = wm * 64 + mi * 16 + g;
            S.part[wn - 2][r]     += s0[mi];
            S.part[wn - 2][r + 8] += s1[mi];
        }
    }
    __syncthreads();

    if (tid < TILE_T) {
        float sc = S.part[0][tid] + S.part[1][tid] + v_b[0];
        if (mask[(size_t)b * NT + t0 + tid]) sc = -CUDART_INF_F;
        g_score[(size_t)b * NT + t0 + tid] = sc;
    }
}

// ---------------------------------------------------------------------------
// Kernel 3: row softmax over T -> alignment (float4, 1024 threads)
// ---------------------------------------------------------------------------
__global__ void softmax_kernel(float* __restrict__ align_out) {
    int b = blockIdx.x;
    int tid = threadIdx.x;
    __shared__ float red[1024];

    const float4* row = (const float4*)&g_score[(size_t)b * NT];
    float4 v = row[tid];
    float m = fmaxf(fmaxf(v.x, v.y), fmaxf(v.z, v.w));
    red[tid] = m;
    __syncthreads();
    for (int s = 512; s > 0; s >>= 1) {
        if (tid < s) red[tid] = fmaxf(red[tid], red[tid + s]);
        __syncthreads();
    }
    m = red[0];
    __syncthreads();

    float4 e;
    e.x = expf(v.x - m);
    e.y = expf(v.y - m);
    e.z = expf(v.z - m);
    e.w = expf(v.w - m);
    red[tid] = e.x + e.y + e.z + e.w;
    __syncthreads();
    for (int s = 512; s > 0; s >>= 1) {
        if (tid < s) red[tid] += red[tid + s];
        __syncthreads();
    }
    float inv = 1.0f / red[0];
    e.x *= inv; e.y *= inv; e.z *= inv; e.w *= inv;
    ((float4*)&align_out[(size_t)b * NT])[tid] = e;
}

// ---------------------------------------------------------------------------
// Kernel 4: context
// ---------------------------------------------------------------------------
__global__ void ctx_init_kernel(float* __restrict__ ctx) {
    ctx[blockIdx.x * NMD + threadIdx.x] = 0.f;
}

#define TCH 256
__global__ void context_kernel(const float* __restrict__ memory,
                               const float* __restrict__ align,
                               float* __restrict__ ctx) {
    int b  = blockIdx.y;
    int tc = blockIdx.x;
    int m  = threadIdx.x;

    __shared__ float al[TCH];
    if (threadIdx.x < TCH)
        al[threadIdx.x] = align[(size_t)b * NT + tc * TCH + threadIdx.x];
    __syncthreads();

    const float* mb = memory + (size_t)b * NT * NMD + (size_t)tc * TCH * NMD;
    float acc = 0.f;
#pragma unroll 8
    for (int t = 0; t < TCH; t++)
        acc = fmaf(al[t], mb[(size_t)t * NMD + m], acc);
    atomicAdd(&ctx[b * NMD + m], acc);
}

// ---------------------------------------------------------------------------
// kernel_launch
// ---------------------------------------------------------------------------
extern "C" void kernel_launch(void* const* d_in, const int* in_sizes, int n_in,
                              void* d_out, int out_size) {
    const float* query      = (const float*)d_in[0];
    const float* memory     = (const float*)d_in[1];
    const float* alignments = (const float*)d_in[2];
    const unsigned char* mask = (const unsigned char*)d_in[3];
    const float* Wq     = (const float*)d_in[4];
    const float* bq     = (const float*)d_in[5];
    const float* Wm     = (const float*)d_in[6];
    const float* bm     = (const float*)d_in[7];
    const float* conv_w = (const float*)d_in[8];
    const float* conv_b = (const float*)d_in[9];
    const float* Wl     = (const float*)d_in[10];
    const float* bl     = (const float*)d_in[11];
    const float* v_w    = (const float*)d_in[12];
    const float* v_b    = (const float*)d_in[13];

    float* out       = (float*)d_out;
    float* out_ctx   = out;                // [NB, NMD]
    float* out_align = out + NB * NMD;     // [NB, NT]

    static bool attr_set = false;
    if (!attr_set) {
        cudaFuncSetAttribute(score_kernel,
                             cudaFuncAttributeMaxDynamicSharedMemorySize,
                             (int)sizeof(ScoreSmem));
        attr_set = true;
    }

    ctx_init_kernel<<<NB, NMD>>>(out_ctx);
    prep_kernel<<<(NMD * NAD + TILE_T * KCH + 255) / 256, 256>>>(Wm, Wl);
    pq_kernel<<<NB, 256>>>(query, Wq, bq);
    score_kernel<<<dim3(NT / TILE_T, NB), 256, sizeof(ScoreSmem)>>>(
        memory, alignments, mask, bm, conv_w, conv_b, bl, v_w, v_b);
    softmax_kernel<<<NB, 1024>>>(out_align);
    context_kernel<<<dim3(NT / TCH, NB), 512>>>(memory, out_align, out_ctx);
}

// round 10
// speedup vs baseline: 2.8118x; 1.0417x over previous
#include <cuda_runtime.h>
#include <cuda_bf16.h>
#include <math.h>
#include <math_constants.h>
#include <stdint.h>

// Problem constants
#define NB   32
#define NT   4096
#define NQD  1024
#define NMD  512
#define NAD  128
#define NF   32
#define NKW  31
#define NPAD 15

// Score-kernel tiling
#define TILE_T  128
#define KCH     32          // K per chunk; loc chunk (Wl, K=32) is chunk 16
#define NCHUNK  16
#define ASTR    40          // padded row stride in elems (80 B, 16B-multiple)
#define NTILES  (NB * (NT / TILE_T))   // 1024 work items

// ---------------------------------------------------------------------------
// Device scratch (no allocation allowed). uint4-typed => 16B alignment.
// ---------------------------------------------------------------------------
__device__ alignas(16) float g_pq[NB * NAD];
__device__ alignas(16) float g_score[NB * NT];
__device__ unsigned g_ticket;
// Pre-split B operands: [chunk][a(128)][k(32)] bf16 packed as uint4 (8 shorts)
__device__ uint4 g_Bhi4[NCHUNK * TILE_T * KCH / 8];
__device__ uint4 g_Blo4[NCHUNK * TILE_T * KCH / 8];
__device__ uint4 g_Wlhi4[TILE_T * KCH / 8];
__device__ uint4 g_Wllo4[TILE_T * KCH / 8];

// ---------------------------------------------------------------------------
// Shared memory: compiler-verified struct; A and B tiles double-buffered.
// ---------------------------------------------------------------------------
struct ScoreSmem {
    alignas(16) unsigned short Ahi[2][TILE_T * ASTR];
    alignas(16) unsigned short Alo[2][TILE_T * ASTR];
    alignas(16) unsigned short Bhi[2][TILE_T * ASTR];
    alignas(16) unsigned short Blo[2][TILE_T * ASTR];
    float pqc[NAD];
    float vw[NAD];
    float al[2][TILE_T + NKW - 1];
    float ws[NF * 2 * NKW];     // 1984 floats
    float cb[NF];
    float part[2][TILE_T];
    unsigned ticket;
};
static_assert(sizeof(ScoreSmem) <= 110 * 1024, "smem overflow");

// ---------------------------------------------------------------------------
// Helpers
// ---------------------------------------------------------------------------
__device__ __forceinline__ uint32_t smem_u32(const void* p) {
    uint32_t r;
    asm("{ .reg .u64 t; cvta.to.shared.u64 t, %1; cvt.u32.u64 %0, t; }"
        : "=r"(r) : "l"(p));
    return r;
}

__device__ __forceinline__ void ldsm4(uint32_t* r, uint32_t addr) {
    asm volatile("ldmatrix.sync.aligned.m8n8.x4.shared.b16 {%0,%1,%2,%3}, [%4];"
                 : "=r"(r[0]), "=r"(r[1]), "=r"(r[2]), "=r"(r[3]) : "r"(addr));
}

__device__ __forceinline__ void mma16816(float* c, const uint32_t* a,
                                         const uint32_t* b) {
    asm volatile(
        "mma.sync.aligned.m16n8k16.row.col.f32.bf16.bf16.f32 "
        "{%0,%1,%2,%3}, {%4,%5,%6,%7}, {%8,%9}, {%0,%1,%2,%3};"
        : "+f"(c[0]), "+f"(c[1]), "+f"(c[2]), "+f"(c[3])
        : "r"(a[0]), "r"(a[1]), "r"(a[2]), "r"(a[3]), "r"(b[0]), "r"(b[1]));
}

#define CP_ASYNC16(dst_u32, src_ptr) \
    asm volatile("cp.async.cg.shared.global [%0], [%1], 16;" \
                 :: "r"(dst_u32), "l"(src_ptr))
#define CP_COMMIT() asm volatile("cp.async.commit_group;")
#define CP_WAIT0()  asm volatile("cp.async.wait_group 0;")

__device__ __forceinline__ void split_bf16(float x, unsigned short& h,
                                           unsigned short& l) {
    __nv_bfloat16 hb = __float2bfloat16(x);
    float hf = __bfloat162float(hb);
    __nv_bfloat16 lb = __float2bfloat16(x - hf);
    h = ((__nv_bfloat16_raw)hb).x;
    l = ((__nv_bfloat16_raw)lb).x;
}

// Fast tanh via MUFU exp; ~1e-7 relative error, clamped for safety.
__device__ __forceinline__ float tanh_fast(float x) {
    x = fminf(fmaxf(x, -20.f), 20.f);
    float e = __expf(-2.f * x);
    return __fdividef(1.f - e, 1.f + e);
}

// ---------------------------------------------------------------------------
// Prep: split Wm / Wl into bf16 hi/lo, [chunk][a][k] linear layout
// ---------------------------------------------------------------------------
__global__ void prep_kernel(const float* __restrict__ Wm,
                            const float* __restrict__ Wl) {
    int idx = blockIdx.x * blockDim.x + threadIdx.x;
    unsigned short* bhi = (unsigned short*)g_Bhi4;
    unsigned short* blo = (unsigned short*)g_Blo4;
    unsigned short* whi = (unsigned short*)g_Wlhi4;
    unsigned short* wlo = (unsigned short*)g_Wllo4;
    if (idx < NMD * NAD) {
        int k = idx >> 7, a = idx & 127;
        int c = k >> 5, kk = k & 31;
        unsigned short h, l;
        split_bf16(Wm[k * NAD + a], h, l);
        int dst = c * (TILE_T * KCH) + a * KCH + kk;
        bhi[dst] = h;
        blo[dst] = l;
    } else if (idx < NMD * NAD + TILE_T * KCH) {
        int r = idx - NMD * NAD;
        int a = r >> 5, kk = r & 31;
        unsigned short h, l;
        split_bf16(Wl[kk * NAD + a], h, l);   // kk < 32 == NF
        whi[a * KCH + kk] = h;
        wlo[a * KCH + kk] = l;
    }
}

// ---------------------------------------------------------------------------
// Kernel 1: processed query + ticket reset + ctx zeroing (folded)
// ---------------------------------------------------------------------------
__global__ void pq_kernel(const float* __restrict__ query,
                          const float* __restrict__ Wq,
                          const float* __restrict__ bq,
                          float* __restrict__ ctx) {
    __shared__ float qs[NQD];
    __shared__ float partial[256];
    int b = blockIdx.x;
    int tid = threadIdx.x;
    if (b == 0 && tid == 0) g_ticket = 0;
    ctx[b * NMD + tid]       = 0.f;
    ctx[b * NMD + 256 + tid] = 0.f;
    for (int i = tid; i < NQD; i += 256)
        qs[i] = query[b * NQD + i];
    __syncthreads();
    int a = tid & 127;
    int h = tid >> 7;
    float acc = 0.f;
    int q0 = h * (NQD / 2);
#pragma unroll 8
    for (int q = 0; q < NQD / 2; q++)
        acc = fmaf(qs[q0 + q], Wq[(q0 + q) * NAD + a], acc);
    partial[tid] = acc;
    __syncthreads();
    if (tid < 128)
        g_pq[b * NAD + a] = bq[a] + partial[tid] + partial[tid + 128];
}

// ---------------------------------------------------------------------------
// Kernel 2: PERSISTENT fused score kernel. Atomic ticket queue over 1024
// tiles; per tile: double-buffered cp.async B + reg-prefetched A, ldmatrix,
// mma.sync bf16 hi/lo 3-product, fused location conv, tanh+v-dot epilogue.
// ---------------------------------------------------------------------------
__global__ __launch_bounds__(256, 2)
void score_kernel(const float* __restrict__ memory,
                  const float* __restrict__ alignments,
                  const unsigned char* __restrict__ mask,
                  const float* __restrict__ bm,
                  const float* __restrict__ conv_w,
                  const float* __restrict__ conv_b,
                  const float* __restrict__ bl,
                  const float* __restrict__ v_w,
                  const float* __restrict__ v_b) {
    extern __shared__ char smem_raw[];
    ScoreSmem& S = *reinterpret_cast<ScoreSmem*>(smem_raw);

    const int tid  = threadIdx.x;
    const int lane = tid & 31;
    const int wid  = tid >> 5;
    const int wm   = wid >> 2;
    const int wn   = wid & 3;
    const int g    = lane >> 2;
    const int tg   = lane & 3;

    // Per-thread A staging geometry (two units of 8 elems each)
    const int tA = tid >> 2;
    const int gA = tid & 3;

    // Tile-invariant loads (once per block)
    for (int i = tid; i < NF * 2 * NKW; i += 256) S.ws[i] = conv_w[i];
    if (tid < NF) S.cb[tid] = conv_b[tid];
    const float vb = *v_b;

    const uint32_t uAhi[2] = {smem_u32(S.Ahi[0]), smem_u32(S.Ahi[1])};
    const uint32_t uAlo[2] = {smem_u32(S.Alo[0]), smem_u32(S.Alo[1])};
    const uint32_t uBhi[2] = {smem_u32(S.Bhi[0]), smem_u32(S.Bhi[1])};
    const uint32_t uBlo[2] = {smem_u32(S.Blo[0]), smem_u32(S.Blo[1])};

    const int iB0 = tid, iB1 = tid + 256;
    const uint32_t offB0 = (uint32_t)(((iB0 >> 2) * ASTR + (iB0 & 3) * 8) * 2);
    const uint32_t offB1 = (uint32_t)(((iB1 >> 2) * ASTR + (iB1 & 3) * 8) * 2);

    // ldmatrix per-lane addressing
    const int aRow  = wm * 64 + (lane & 15);
    const int aColX = (lane >> 4) * 8;
    const int bRow  = wn * 32 + ((lane >> 4) << 3) + (lane & 7);
    const int bColX = ((lane >> 3) & 1) * 8;

    float4 a4[2][2];
    const float* memb = memory;   // set per tile

    auto convertA = [&](int buf) {
#pragma unroll
        for (int u = 0; u < 2; u++) {
            float f[8] = {a4[u][0].x, a4[u][0].y, a4[u][0].z, a4[u][0].w,
                          a4[u][1].x, a4[u][1].y, a4[u][1].z, a4[u][1].w};
            uint32_t hw[4], lw[4];
#pragma unroll
            for (int j = 0; j < 4; j++) {
                unsigned short h0, l0, h1, l1;
                split_bf16(f[2 * j],     h0, l0);
                split_bf16(f[2 * j + 1], h1, l1);
                hw[j] = (uint32_t)h0 | ((uint32_t)h1 << 16);
                lw[j] = (uint32_t)l0 | ((uint32_t)l1 << 16);
            }
            int off = (tA + u * 64) * ASTR + gA * 8;
            *(uint4*)&S.Ahi[buf][off] = make_uint4(hw[0], hw[1], hw[2], hw[3]);
            *(uint4*)&S.Alo[buf][off] = make_uint4(lw[0], lw[1], lw[2], lw[3]);
        }
    };
    auto loadA = [&](int c) {
#pragma unroll
        for (int u = 0; u < 2; u++) {
            const float* src = memb + (size_t)(tA + u * 64) * NMD + c * KCH + gA * 8;
            a4[u][0] = *(const float4*)src;
            a4[u][1] = *(const float4*)(src + 4);
        }
    };
    auto stageB = [&](int c) {
        const uint4* shp = (c < NCHUNK) ? (g_Bhi4 + c * 512) : g_Wlhi4;
        const uint4* slp = (c < NCHUNK) ? (g_Blo4 + c * 512) : g_Wllo4;
        const int nb = c & 1;
        CP_ASYNC16(uBhi[nb] + offB0, shp + iB0);
        CP_ASYNC16(uBhi[nb] + offB1, shp + iB1);
        CP_ASYNC16(uBlo[nb] + offB0, slp + iB0);
        CP_ASYNC16(uBlo[nb] + offB1, slp + iB1);
        CP_COMMIT();
    };

    // ======================= persistent tile loop =======================
    while (true) {
        if (tid == 0) S.ticket = atomicAdd(&g_ticket, 1u);
        __syncthreads();                 // publish ticket; fence prev tile
        const unsigned tile = S.ticket;
        if (tile >= NTILES) break;
        const int b  = (int)(tile >> 5);
        const int t0 = (int)(tile & 31) * TILE_T;

        // per-tile prologue
        for (int i = tid; i < 2 * (TILE_T + NKW - 1); i += 256) {
            int c = i / (TILE_T + NKW - 1);
            int p = i % (TILE_T + NKW - 1);
            int t = t0 - NPAD + p;
            S.al[c][p] = (t >= 0 && t < NT)
                       ? alignments[((size_t)b * NT + t) * 2 + c] : 0.f;
        }
        if (tid < NAD) {
            S.pqc[tid] = g_pq[b * NAD + tid] + bm[tid] + bl[tid];
            S.vw[tid]  = v_w[tid];
        }
        memb = memory + ((size_t)b * NT + t0) * NMD;

        float acc[4][4][4];
#pragma unroll
        for (int mi = 0; mi < 4; mi++)
#pragma unroll
            for (int ni = 0; ni < 4; ni++)
#pragma unroll
                for (int j = 0; j < 4; j++) acc[mi][ni][j] = 0.f;

        // Prologue: stage chunk 0
        stageB(0);
        loadA(0);
        convertA(0);
        loadA(1);

        for (int c = 0; c <= NCHUNK; c++) {
            const int nc = c + 1;
            CP_WAIT0();
            __syncthreads();   // publish B(c)+A(c); fence MMA(c-1) reads
            if (nc <= NCHUNK) stageB(nc);
            if (nc < NCHUNK) {
                convertA(nc & 1);
                if (nc + 1 < NCHUNK) loadA(nc + 1);
            } else if (nc == NCHUNK) {
                // loc chunk: conv -> bf16 hi/lo into buffer 0 (16&1==0)
                for (int idx = tid; idx < TILE_T * NF; idx += 256) {
                    int t = idx >> 5, f = idx & 31;
                    float v = S.cb[f];
                    const float* wf = &S.ws[f * 2 * NKW];
#pragma unroll
                    for (int cc = 0; cc < 2; cc++)
#pragma unroll
                        for (int k = 0; k < NKW; k++)
                            v = fmaf(S.al[cc][t + k], wf[cc * NKW + k], v);
                    unsigned short h, l;
                    split_bf16(v, h, l);
                    S.Ahi[0][t * ASTR + f] = h;
                    S.Alo[0][t * ASTR + f] = l;
                }
            }
            // MMA on chunk c
            const uint32_t uAh = uAhi[c & 1], uAl = uAlo[c & 1];
            const uint32_t uBh = uBhi[c & 1], uBl = uBlo[c & 1];
#pragma unroll
            for (int ks = 0; ks < 2; ks++) {
                const int k0 = ks * 16;
                uint32_t bh[8], blr[8];
                {
                    uint32_t ab = uBh + (uint32_t)((bRow * ASTR + k0 + bColX) * 2);
                    ldsm4(bh,     ab);
                    ldsm4(bh + 4, ab + 16 * ASTR * 2);
                    uint32_t ab2 = uBl + (uint32_t)((bRow * ASTR + k0 + bColX) * 2);
                    ldsm4(blr,     ab2);
                    ldsm4(blr + 4, ab2 + 16 * ASTR * 2);
                }
#pragma unroll
                for (int mi = 0; mi < 4; mi++) {
                    uint32_t aoff =
                        (uint32_t)(((aRow + mi * 16) * ASTR + k0 + aColX) * 2);
                    uint32_t ah[4], alr[4];
                    ldsm4(ah,  uAh + aoff);
                    ldsm4(alr, uAl + aoff);
#pragma unroll
                    for (int ni = 0; ni < 4; ni++) {
                        mma16816(acc[mi][ni], ah,  &bh[ni * 2]);
                        mma16816(acc[mi][ni], ah,  &blr[ni * 2]);
                        mma16816(acc[mi][ni], alr, &bh[ni * 2]);
                    }
                }
            }
        }

        // Epilogue: tanh + v-dot, lane-group reduce, 2-stage warp reduce
        float s0[4], s1[4];
#pragma unroll
        for (int mi = 0; mi < 4; mi++) {
            float p0 = 0.f, p1 = 0.f;
#pragma unroll
            for (int ni = 0; ni < 4; ni++) {
#pragma unroll
                for (int j = 0; j < 2; j++) {
                    int cdx = wn * 32 + ni * 8 + tg * 2 + j;
                    p0 = fmaf(S.vw[cdx], tanh_fast(acc[mi][ni][j]     + S.pqc[cdx]), p0);
                    p1 = fmaf(S.vw[cdx], tanh_fast(acc[mi][ni][2 + j] + S.pqc[cdx]), p1);
                }
            }
            p0 += __shfl_xor_sync(0xffffffffu, p0, 1);
            p0 += __shfl_xor_sync(0xffffffffu, p0, 2);
            p1 += __shfl_xor_sync(0xffffffffu, p1, 1);
            p1 += __shfl_xor_sync(0xffffffffu, p1, 2);
            s0[mi] = p0;
            s1[mi] = p1;
        }
        __syncthreads();
        if (wn < 2 && tg == 0) {
#pragma unroll
            for (int mi = 0; mi < 4; mi++) {
                int r = wm * 64 + mi * 16 + g;
                S.part[wn][r]     = s0[mi];
                S.part[wn][r + 8] = s1[mi];
            }
        }
        __syncthreads();
        if (wn >= 2 && tg == 0) {
#pragma unroll
            for (int mi = 0; mi < 4; mi++) {
                int r = wm * 64 + mi * 16 + g;
                S.part[wn - 2][r]     += s0[mi];
                S.part[wn - 2][r + 8] += s1[mi];
            }
        }
        __syncthreads();

        if (tid < TILE_T) {
            float sc = S.part[0][tid] + S.part[1][tid] + vb;
            if (mask[(size_t)b * NT + t0 + tid]) sc = -CUDART_INF_F;
            g_score[(size_t)b * NT + t0 + tid] = sc;
        }
        // ticket __syncthreads() at loop top fences before next tile's writes
    }
}

// ---------------------------------------------------------------------------
// Kernel 3: row softmax over T -> alignment (float4, 1024 threads)
// ---------------------------------------------------------------------------
__global__ void softmax_kernel(float* __restrict__ align_out) {
    int b = blockIdx.x;
    int tid = threadIdx.x;
    __shared__ float red[1024];

    const float4* row = (const float4*)&g_score[(size_t)b * NT];
    float4 v = row[tid];
    float m = fmaxf(fmaxf(v.x, v.y), fmaxf(v.z, v.w));
    red[tid] = m;
    __syncthreads();
    for (int s = 512; s > 0; s >>= 1) {
        if (tid < s) red[tid] = fmaxf(red[tid], red[tid + s]);
        __syncthreads();
    }
    m = red[0];
    __syncthreads();

    float4 e;
    e.x = expf(v.x - m);
    e.y = expf(v.y - m);
    e.z = expf(v.z - m);
    e.w = expf(v.w - m);
    red[tid] = e.x + e.y + e.z + e.w;
    __syncthreads();
    for (int s = 512; s > 0; s >>= 1) {
        if (tid < s) red[tid] += red[tid + s];
        __syncthreads();
    }
    float inv = 1.0f / red[0];
    e.x *= inv; e.y *= inv; e.z *= inv; e.w *= inv;
    ((float4*)&align_out[(size_t)b * NT])[tid] = e;
}

// ---------------------------------------------------------------------------
// Kernel 4: context (float4 vectorized, 2 t-halves x 128 m-quads)
// ---------------------------------------------------------------------------
#define TCH 256
__global__ void context_kernel(const float* __restrict__ memory,
                               const float* __restrict__ align,
                               float* __restrict__ ctx) {
    int b  = blockIdx.y;
    int tc = blockIdx.x;
    int m4 = threadIdx.x & 127;   // float4 column group (512/4 = 128)
    int th = threadIdx.x >> 7;    // 0..1 t-half

    __shared__ float al[TCH];
    __shared__ float4 red[128];
    if (threadIdx.x < TCH)
        al[threadIdx.x] = align[(size_t)b * NT + tc * TCH + threadIdx.x];
    __syncthreads();

    const float4* mb = (const float4*)(memory +
        (size_t)b * NT * NMD + (size_t)(tc * TCH + th * 128) * NMD);
    float4 acc = make_float4(0.f, 0.f, 0.f, 0.f);
    const float* alh = &al[th * 128];
#pragma unroll 4
    for (int t = 0; t < 128; t++) {
        float a = alh[t];
        float4 v = mb[(size_t)t * 128 + m4];
        acc.x = fmaf(a, v.x, acc.x);
        acc.y = fmaf(a, v.y, acc.y);
        acc.z = fmaf(a, v.z, acc.z);
        acc.w = fmaf(a, v.w, acc.w);
    }
    if (th == 1) red[m4] = acc;
    __syncthreads();
    if (th == 0) {
        float4 o = red[m4];
        acc.x += o.x; acc.y += o.y; acc.z += o.z; acc.w += o.w;
        float* dst = &ctx[b * NMD + m4 * 4];
        atomicAdd(dst + 0, acc.x);
        atomicAdd(dst + 1, acc.y);
        atomicAdd(dst + 2, acc.z);
        atomicAdd(dst + 3, acc.w);
    }
}

// ---------------------------------------------------------------------------
// kernel_launch
// ---------------------------------------------------------------------------
extern "C" void kernel_launch(void* const* d_in, const int* in_sizes, int n_in,
                              void* d_out, int out_size) {
    const float* query      = (const float*)d_in[0];
    const float* memory     = (const float*)d_in[1];
    const float* alignments = (const float*)d_in[2];
    const unsigned char* mask = (const unsigned char*)d_in[3];
    const float* Wq     = (const float*)d_in[4];
    const float* bq     = (const float*)d_in[5];
    const float* Wm     = (const float*)d_in[6];
    const float* bm     = (const float*)d_in[7];
    const float* conv_w = (const float*)d_in[8];
    const float* conv_b = (const float*)d_in[9];
    const float* Wl     = (const float*)d_in[10];
    const float* bl     = (const float*)d_in[11];
    const float* v_w    = (const float*)d_in[12];
    const float* v_b    = (const float*)d_in[13];

    float* out       = (float*)d_out;
    float* out_ctx   = out;                // [NB, NMD]
    float* out_align = out + NB * NMD;     // [NB, NT]

    static int nblocks = 0;
    if (!nblocks) {
        cudaFuncSetAttribute(score_kernel,
                             cudaFuncAttributeMaxDynamicSharedMemorySize,
                             (int)sizeof(ScoreSmem));
        int sm = 148;
        cudaDeviceGetAttribute(&sm, cudaDevAttrMultiProcessorCount, 0);
        nblocks = 2 * sm;
    }

    prep_kernel<<<(NMD * NAD + TILE_T * KCH + 255) / 256, 256>>>(Wm, Wl);
    pq_kernel<<<NB, 256>>>(query, Wq, bq, out_ctx);
    score_kernel<<<nblocks, 256, sizeof(ScoreSmem)>>>(
        memory, alignments, mask, bm, conv_w, conv_b, bl, v_w, v_b);
    softmax_kernel<<<NB, 1024>>>(out_align);
    context_kernel<<<dim3(NT / TCH, NB), 256>>>(memory, out_align, out_ctx);
}

// round 11
// speedup vs baseline: 3.3263x; 1.1830x over previous
#include <cuda_runtime.h>
#include <cuda_fp16.h>
#include <math.h>
#include <math_constants.h>
#include <stdint.h>

// Problem constants
#define NB   32
#define NT   4096
#define NQD  1024
#define NMD  512
#define NAD  128
#define NF   32
#define NKW  31
#define NPAD 15

// Score-kernel tiling
#define TILE_T  128
#define KCH     32          // K per chunk; loc chunk (Wl, K=32) is chunk 16
#define NCHUNK  16
#define ASTR    40          // padded row stride in elems (80 B, 16B-multiple)
#define NTILES  (NB * (NT / TILE_T))   // 1024 work items

// ---------------------------------------------------------------------------
// Device scratch (no allocation allowed). uint4-typed => 16B alignment.
// ---------------------------------------------------------------------------
__device__ alignas(16) float g_pq[NB * NAD];
__device__ alignas(16) float g_score[NB * NT];
__device__ unsigned g_ticket;
// Pre-split B operands (fp16 hi/lo): [chunk][a(128)][k(32)] packed as uint4
__device__ uint4 g_Bhi4[NCHUNK * TILE_T * KCH / 8];
__device__ uint4 g_Blo4[NCHUNK * TILE_T * KCH / 8];
__device__ uint4 g_Wlhi4[TILE_T * KCH / 8];
__device__ uint4 g_Wllo4[TILE_T * KCH / 8];

// ---------------------------------------------------------------------------
// Shared memory: A single-precision-split only for loc; fp16 tiles.
// ---------------------------------------------------------------------------
struct ScoreSmem {
    alignas(16) unsigned short Ahi[2][TILE_T * ASTR];   // fp16 A (memory / loc hi)
    alignas(16) unsigned short Alo[TILE_T * ASTR];      // fp16 A lo (loc chunk only)
    alignas(16) unsigned short Bhi[2][TILE_T * ASTR];
    alignas(16) unsigned short Blo[2][TILE_T * ASTR];
    float pqc[NAD];
    float vw[NAD];
    float al[2][TILE_T + NKW - 1];
    float ws[NF * 2 * NKW];     // 1984 floats
    float cb[NF];
    float part[2][TILE_T];
    unsigned ticket;
};
static_assert(sizeof(ScoreSmem) <= 110 * 1024, "smem overflow");

// ---------------------------------------------------------------------------
// Helpers
// ---------------------------------------------------------------------------
__device__ __forceinline__ uint32_t smem_u32(const void* p) {
    uint32_t r;
    asm("{ .reg .u64 t; cvta.to.shared.u64 t, %1; cvt.u32.u64 %0, t; }"
        : "=r"(r) : "l"(p));
    return r;
}

__device__ __forceinline__ void ldsm4(uint32_t* r, uint32_t addr) {
    asm volatile("ldmatrix.sync.aligned.m8n8.x4.shared.b16 {%0,%1,%2,%3}, [%4];"
                 : "=r"(r[0]), "=r"(r[1]), "=r"(r[2]), "=r"(r[3]) : "r"(addr));
}

__device__ __forceinline__ void mma16816(float* c, const uint32_t* a,
                                         const uint32_t* b) {
    asm volatile(
        "mma.sync.aligned.m16n8k16.row.col.f32.f16.f16.f32 "
        "{%0,%1,%2,%3}, {%4,%5,%6,%7}, {%8,%9}, {%0,%1,%2,%3};"
        : "+f"(c[0]), "+f"(c[1]), "+f"(c[2]), "+f"(c[3])
        : "r"(a[0]), "r"(a[1]), "r"(a[2]), "r"(a[3]), "r"(b[0]), "r"(b[1]));
}

#define CP_ASYNC16(dst_u32, src_ptr) \
    asm volatile("cp.async.cg.shared.global [%0], [%1], 16;" \
                 :: "r"(dst_u32), "l"(src_ptr))
#define CP_COMMIT() asm volatile("cp.async.commit_group;")
#define CP_WAIT0()  asm volatile("cp.async.wait_group 0;")

__device__ __forceinline__ void split_fp16(float x, unsigned short& h,
                                           unsigned short& l) {
    __half hb = __float2half_rn(x);
    __half lb = __float2half_rn(x - __half2float(hb));
    h = ((__half_raw)hb).x;
    l = ((__half_raw)lb).x;
}

__device__ __forceinline__ float tanh_fast(float x) {
    x = fminf(fmaxf(x, -20.f), 20.f);
    float e = __expf(-2.f * x);
    return __fdividef(1.f - e, 1.f + e);
}

// ---------------------------------------------------------------------------
// Prep: split Wm / Wl into fp16 hi/lo, [chunk][a][k] linear layout
// ---------------------------------------------------------------------------
__global__ void prep_kernel(const float* __restrict__ Wm,
                            const float* __restrict__ Wl) {
    int idx = blockIdx.x * blockDim.x + threadIdx.x;
    unsigned short* bhi = (unsigned short*)g_Bhi4;
    unsigned short* blo = (unsigned short*)g_Blo4;
    unsigned short* whi = (unsigned short*)g_Wlhi4;
    unsigned short* wlo = (unsigned short*)g_Wllo4;
    if (idx < NMD * NAD) {
        int k = idx >> 7, a = idx & 127;
        int c = k >> 5, kk = k & 31;
        unsigned short h, l;
        split_fp16(Wm[k * NAD + a], h, l);
        int dst = c * (TILE_T * KCH) + a * KCH + kk;
        bhi[dst] = h;
        blo[dst] = l;
    } else if (idx < NMD * NAD + TILE_T * KCH) {
        int r = idx - NMD * NAD;
        int a = r >> 5, kk = r & 31;
        unsigned short h, l;
        split_fp16(Wl[kk * NAD + a], h, l);   // kk < 32 == NF
        whi[a * KCH + kk] = h;
        wlo[a * KCH + kk] = l;
    }
}

// ---------------------------------------------------------------------------
// Kernel 1: processed query + ticket reset + ctx zeroing (folded)
// ---------------------------------------------------------------------------
__global__ void pq_kernel(const float* __restrict__ query,
                          const float* __restrict__ Wq,
                          const float* __restrict__ bq,
                          float* __restrict__ ctx) {
    __shared__ float qs[NQD];
    __shared__ float partial[256];
    int b = blockIdx.x;
    int tid = threadIdx.x;
    if (b == 0 && tid == 0) g_ticket = 0;
    ctx[b * NMD + tid]       = 0.f;
    ctx[b * NMD + 256 + tid] = 0.f;
    for (int i = tid; i < NQD; i += 256)
        qs[i] = query[b * NQD + i];
    __syncthreads();
    int a = tid & 127;
    int h = tid >> 7;
    float acc = 0.f;
    int q0 = h * (NQD / 2);
#pragma unroll 8
    for (int q = 0; q < NQD / 2; q++)
        acc = fmaf(qs[q0 + q], Wq[(q0 + q) * NAD + a], acc);
    partial[tid] = acc;
    __syncthreads();
    if (tid < 128)
        g_pq[b * NAD + a] = bq[a] + partial[tid] + partial[tid + 128];
}

// ---------------------------------------------------------------------------
// Kernel 2: PERSISTENT fused score kernel. fp16 2-product mainloop
// (A single fp16, B=Wm split hi/lo), loc chunk 3-product. Double-buffered
// cp.async B + reg-prefetched A, stage/convert interleaved between ks steps.
// ---------------------------------------------------------------------------
__global__ __launch_bounds__(256, 2)
void score_kernel(const float* __restrict__ memory,
                  const float* __restrict__ alignments,
                  const unsigned char* __restrict__ mask,
                  const float* __restrict__ bm,
                  const float* __restrict__ conv_w,
                  const float* __restrict__ conv_b,
                  const float* __restrict__ bl,
                  const float* __restrict__ v_w,
                  const float* __restrict__ v_b) {
    extern __shared__ char smem_raw[];
    ScoreSmem& S = *reinterpret_cast<ScoreSmem*>(smem_raw);

    const int tid  = threadIdx.x;
    const int lane = tid & 31;
    const int wid  = tid >> 5;
    const int wm   = wid >> 2;
    const int wn   = wid & 3;
    const int g    = lane >> 2;
    const int tg   = lane & 3;

    const int tA = tid >> 2;
    const int gA = tid & 3;

    for (int i = tid; i < NF * 2 * NKW; i += 256) S.ws[i] = conv_w[i];
    if (tid < NF) S.cb[tid] = conv_b[tid];
    const float vb = *v_b;

    const uint32_t uAhi[2] = {smem_u32(S.Ahi[0]), smem_u32(S.Ahi[1])};
    const uint32_t uAloS  = smem_u32(S.Alo);
    const uint32_t uBhi[2] = {smem_u32(S.Bhi[0]), smem_u32(S.Bhi[1])};
    const uint32_t uBlo[2] = {smem_u32(S.Blo[0]), smem_u32(S.Blo[1])};

    const int iB0 = tid, iB1 = tid + 256;
    const uint32_t offB0 = (uint32_t)(((iB0 >> 2) * ASTR + (iB0 & 3) * 8) * 2);
    const uint32_t offB1 = (uint32_t)(((iB1 >> 2) * ASTR + (iB1 & 3) * 8) * 2);

    // ldmatrix per-lane addressing
    const int aRow  = wm * 64 + (lane & 15);
    const int aColX = (lane >> 4) * 8;
    const int bRow  = wn * 32 + ((lane >> 4) << 3) + (lane & 7);
    const int bColX = ((lane >> 3) & 1) * 8;

    float4 a4[2][2];
    const float* memb = memory;

    auto convertA = [&](int buf) {    // fp16 single-precision A convert
#pragma unroll
        for (int u = 0; u < 2; u++) {
            __half2 h0 = __floats2half2_rn(a4[u][0].x, a4[u][0].y);
            __half2 h1 = __floats2half2_rn(a4[u][0].z, a4[u][0].w);
            __half2 h2 = __floats2half2_rn(a4[u][1].x, a4[u][1].y);
            __half2 h3 = __floats2half2_rn(a4[u][1].z, a4[u][1].w);
            int off = (tA + u * 64) * ASTR + gA * 8;
            *(uint4*)&S.Ahi[buf][off] = make_uint4(
                *(uint32_t*)&h0, *(uint32_t*)&h1,
                *(uint32_t*)&h2, *(uint32_t*)&h3);
        }
    };
    auto loadA = [&](int c) {
#pragma unroll
        for (int u = 0; u < 2; u++) {
            const float* src = memb + (size_t)(tA + u * 64) * NMD + c * KCH + gA * 8;
            a4[u][0] = *(const float4*)src;
            a4[u][1] = *(const float4*)(src + 4);
        }
    };
    auto stageB = [&](int c) {
        const uint4* shp = (c < NCHUNK) ? (g_Bhi4 + c * 512) : g_Wlhi4;
        const uint4* slp = (c < NCHUNK) ? (g_Blo4 + c * 512) : g_Wllo4;
        const int nb = c & 1;
        CP_ASYNC16(uBhi[nb] + offB0, shp + iB0);
        CP_ASYNC16(uBhi[nb] + offB1, shp + iB1);
        CP_ASYNC16(uBlo[nb] + offB0, slp + iB0);
        CP_ASYNC16(uBlo[nb] + offB1, slp + iB1);
        CP_COMMIT();
    };

    // One K16 MMA step (2-product); optional 3rd product from Alo (loc chunk)
    auto mmaStep = [&](float acc[4][4][4], int k0, uint32_t uAh,
                       uint32_t uBh, uint32_t uBl, bool loc) {
        uint32_t bh[8], blr[8];
        uint32_t ab = uBh + (uint32_t)((bRow * ASTR + k0 + bColX) * 2);
        ldsm4(bh,     ab);
        ldsm4(bh + 4, ab + 16 * ASTR * 2);
        uint32_t ab2 = uBl + (uint32_t)((bRow * ASTR + k0 + bColX) * 2);
        ldsm4(blr,     ab2);
        ldsm4(blr + 4, ab2 + 16 * ASTR * 2);
#pragma unroll
        for (int mi = 0; mi < 4; mi++) {
            uint32_t aoff = (uint32_t)(((aRow + mi * 16) * ASTR + k0 + aColX) * 2);
            uint32_t ah[4];
            ldsm4(ah, uAh + aoff);
            uint32_t al[4];
            if (loc) ldsm4(al, uAloS + aoff);
#pragma unroll
            for (int ni = 0; ni < 4; ni++) {
                mma16816(acc[mi][ni], ah, &bh[ni * 2]);
                mma16816(acc[mi][ni], ah, &blr[ni * 2]);
                if (loc) mma16816(acc[mi][ni], al, &bh[ni * 2]);
            }
        }
    };

    // ======================= persistent tile loop =======================
    while (true) {
        if (tid == 0) S.ticket = atomicAdd(&g_ticket, 1u);
        __syncthreads();                 // publish ticket; fence prev tile
        const unsigned tile = S.ticket;
        if (tile >= NTILES) break;
        const int b  = (int)(tile >> 5);
        const int t0 = (int)(tile & 31) * TILE_T;

        for (int i = tid; i < 2 * (TILE_T + NKW - 1); i += 256) {
            int c = i / (TILE_T + NKW - 1);
            int p = i % (TILE_T + NKW - 1);
            int t = t0 - NPAD + p;
            S.al[c][p] = (t >= 0 && t < NT)
                       ? alignments[((size_t)b * NT + t) * 2 + c] : 0.f;
        }
        if (tid < NAD) {
            S.pqc[tid] = g_pq[b * NAD + tid] + bm[tid] + bl[tid];
            S.vw[tid]  = v_w[tid];
        }
        memb = memory + ((size_t)b * NT + t0) * NMD;

        float acc[4][4][4];
#pragma unroll
        for (int mi = 0; mi < 4; mi++)
#pragma unroll
            for (int ni = 0; ni < 4; ni++)
#pragma unroll
                for (int j = 0; j < 4; j++) acc[mi][ni][j] = 0.f;

        stageB(0);
        loadA(0);
        convertA(0);
        loadA(1);

        // --- memory chunks 0..15, 2-product fp16 ---
        for (int c = 0; c < NCHUNK; c++) {
            const int nc = c + 1;
            CP_WAIT0();
            __syncthreads();   // publish B(c)+A(c); fence MMA(c-1) reads
            const uint32_t uAh = uAhi[c & 1];
            const uint32_t uBh = uBhi[c & 1], uBl = uBlo[c & 1];
            // ks0
            mmaStep(acc, 0, uAh, uBh, uBl, false);
            // middle: stage/convert next chunk (fills tensor-idle slots)
            stageB(nc);
            if (nc < NCHUNK) {
                convertA(nc & 1);
                if (nc + 1 < NCHUNK) loadA(nc + 1);
            } else {
                // loc chunk (nc == 16): conv -> fp16 hi/lo into Ahi[0]/Alo
                for (int idx = tid; idx < TILE_T * NF; idx += 256) {
                    int t = idx >> 5, f = idx & 31;
                    float v = S.cb[f];
                    const float* wf = &S.ws[f * 2 * NKW];
#pragma unroll
                    for (int cc = 0; cc < 2; cc++)
#pragma unroll
                        for (int k = 0; k < NKW; k++)
                            v = fmaf(S.al[cc][t + k], wf[cc * NKW + k], v);
                    unsigned short h, l;
                    split_fp16(v, h, l);
                    S.Ahi[0][t * ASTR + f] = h;
                    S.Alo[t * ASTR + f]    = l;
                }
            }
            // ks1
            mmaStep(acc, 16, uAh, uBh, uBl, false);
        }

        // --- loc chunk (chunk 16, buffer 0), 3-product fp16 ---
        CP_WAIT0();
        __syncthreads();
        mmaStep(acc, 0,  uAhi[0], uBhi[0], uBlo[0], true);
        mmaStep(acc, 16, uAhi[0], uBhi[0], uBlo[0], true);

        // Epilogue: tanh + v-dot, lane-group reduce, 2-stage warp reduce
        float s0[4], s1[4];
#pragma unroll
        for (int mi = 0; mi < 4; mi++) {
            float p0 = 0.f, p1 = 0.f;
#pragma unroll
            for (int ni = 0; ni < 4; ni++) {
#pragma unroll
                for (int j = 0; j < 2; j++) {
                    int cdx = wn * 32 + ni * 8 + tg * 2 + j;
                    p0 = fmaf(S.vw[cdx], tanh_fast(acc[mi][ni][j]     + S.pqc[cdx]), p0);
                    p1 = fmaf(S.vw[cdx], tanh_fast(acc[mi][ni][2 + j] + S.pqc[cdx]), p1);
                }
            }
            p0 += __shfl_xor_sync(0xffffffffu, p0, 1);
            p0 += __shfl_xor_sync(0xffffffffu, p0, 2);
            p1 += __shfl_xor_sync(0xffffffffu, p1, 1);
            p1 += __shfl_xor_sync(0xffffffffu, p1, 2);
            s0[mi] = p0;
            s1[mi] = p1;
        }
        __syncthreads();
        if (wn < 2 && tg == 0) {
#pragma unroll
            for (int mi = 0; mi < 4; mi++) {
                int r = wm * 64 + mi * 16 + g;
                S.part[wn][r]     = s0[mi];
                S.part[wn][r + 8] = s1[mi];
            }
        }
        __syncthreads();
        if (wn >= 2 && tg == 0) {
#pragma unroll
            for (int mi = 0; mi < 4; mi++) {
                int r = wm * 64 + mi * 16 + g;
                S.part[wn - 2][r]     += s0[mi];
                S.part[wn - 2][r + 8] += s1[mi];
            }
        }
        __syncthreads();

        if (tid < TILE_T) {
            float sc = S.part[0][tid] + S.part[1][tid] + vb;
            if (mask[(size_t)b * NT + t0 + tid]) sc = -CUDART_INF_F;
            g_score[(size_t)b * NT + t0 + tid] = sc;
        }
    }
}

// ---------------------------------------------------------------------------
// Kernel 3: row softmax over T -> alignment (float4, 1024 threads)
// ---------------------------------------------------------------------------
__global__ void softmax_kernel(float* __restrict__ align_out) {
    int b = blockIdx.x;
    int tid = threadIdx.x;
    __shared__ float red[1024];

    const float4* row = (const float4*)&g_score[(size_t)b * NT];
    float4 v = row[tid];
    float m = fmaxf(fmaxf(v.x, v.y), fmaxf(v.z, v.w));
    red[tid] = m;
    __syncthreads();
    for (int s = 512; s > 0; s >>= 1) {
        if (tid < s) red[tid] = fmaxf(red[tid], red[tid + s]);
        __syncthreads();
    }
    m = red[0];
    __syncthreads();

    float4 e;
    e.x = expf(v.x - m);
    e.y = expf(v.y - m);
    e.z = expf(v.z - m);
    e.w = expf(v.w - m);
    red[tid] = e.x + e.y + e.z + e.w;
    __syncthreads();
    for (int s = 512; s > 0; s >>= 1) {
        if (tid < s) red[tid] += red[tid + s];
        __syncthreads();
    }
    float inv = 1.0f / red[0];
    e.x *= inv; e.y *= inv; e.z *= inv; e.w *= inv;
    ((float4*)&align_out[(size_t)b * NT])[tid] = e;
}

// ---------------------------------------------------------------------------
// Kernel 4: context (float4 vectorized, 2 t-halves x 128 m-quads)
// ---------------------------------------------------------------------------
#define TCH 256
__global__ void context_kernel(const float* __restrict__ memory,
                               const float* __restrict__ align,
                               float* __restrict__ ctx) {
    int b  = blockIdx.y;
    int tc = blockIdx.x;
    int m4 = threadIdx.x & 127;
    int th = threadIdx.x >> 7;

    __shared__ float al[TCH];
    __shared__ float4 red[128];
    if (threadIdx.x < TCH)
        al[threadIdx.x] = align[(size_t)b * NT + tc * TCH + threadIdx.x];
    __syncthreads();

    const float4* mb = (const float4*)(memory +
        (size_t)b * NT * NMD + (size_t)(tc * TCH + th * 128) * NMD);
    float4 acc = make_float4(0.f, 0.f, 0.f, 0.f);
    const float* alh = &al[th * 128];
#pragma unroll 4
    for (int t = 0; t < 128; t++) {
        float a = alh[t];
        float4 v = mb[(size_t)t * 128 + m4];
        acc.x = fmaf(a, v.x, acc.x);
        acc.y = fmaf(a, v.y, acc.y);
        acc.z = fmaf(a, v.z, acc.z);
        acc.w = fmaf(a, v.w, acc.w);
    }
    if (th == 1) red[m4] = acc;
    __syncthreads();
    if (th == 0) {
        float4 o = red[m4];
        acc.x += o.x; acc.y += o.y; acc.z += o.z; acc.w += o.w;
        float* dst = &ctx[b * NMD + m4 * 4];
        atomicAdd(dst + 0, acc.x);
        atomicAdd(dst + 1, acc.y);
        atomicAdd(dst + 2, acc.z);
        atomicAdd(dst + 3, acc.w);
    }
}

// ---------------------------------------------------------------------------
// kernel_launch
// ---------------------------------------------------------------------------
extern "C" void kernel_launch(void* const* d_in, const int* in_sizes, int n_in,
                              void* d_out, int out_size) {
    const float* query      = (const float*)d_in[0];
    const float* memory     = (const float*)d_in[1];
    const float* alignments = (const float*)d_in[2];
    const unsigned char* mask = (const unsigned char*)d_in[3];
    const float* Wq     = (const float*)d_in[4];
    const float* bq     = (const float*)d_in[5];
    const float* Wm     = (const float*)d_in[6];
    const float* bm     = (const float*)d_in[7];
    const float* conv_w = (const float*)d_in[8];
    const float* conv_b = (const float*)d_in[9];
    const float* Wl     = (const float*)d_in[10];
    const float* bl     = (const float*)d_in[11];
    const float* v_w    = (const float*)d_in[12];
    const float* v_b    = (const float*)d_in[13];

    float* out       = (float*)d_out;
    float* out_ctx   = out;                // [NB, NMD]
    float* out_align = out + NB * NMD;     // [NB, NT]

    static int nblocks = 0;
    if (!nblocks) {
        cudaFuncSetAttribute(score_kernel,
                             cudaFuncAttributeMaxDynamicSharedMemorySize,
                             (int)sizeof(ScoreSmem));
        int sm = 148;
        cudaDeviceGetAttribute(&sm, cudaDevAttrMultiProcessorCount, 0);
        nblocks = 2 * sm;
    }

    prep_kernel<<<(NMD * NAD + TILE_T * KCH + 255) / 256, 256>>>(Wm, Wl);
    pq_kernel<<<NB, 256>>>(query, Wq, bq, out_ctx);
    score_kernel<<<nblocks, 256, sizeof(ScoreSmem)>>>(
        memory, alignments, mask, bm, conv_w, conv_b, bl, v_w, v_b);
    softmax_kernel<<<NB, 1024>>>(out_align);
    context_kernel<<<dim3(NT / TCH, NB), 256>>>(memory, out_align, out_ctx);
}

// round 12
// speedup vs baseline: 3.8031x; 1.1434x over previous
#include <cuda_runtime.h>
#include <cuda_fp16.h>
#include <math.h>
#include <math_constants.h>
#include <stdint.h>

// Problem constants
#define NB   32
#define NT   4096
#define NQD  1024
#define NMD  512
#define NAD  128
#define NF   32
#define NKW  31
#define NPAD 15

// Score-kernel tiling
#define TILE_T  128
#define KCH     32          // K per chunk; loc chunk (Wl, K=32) is chunk 16
#define NCHUNK  16
#define ASTR    40          // padded row stride in elems (80 B, 16B-multiple)
#define NTILES  (NB * (NT / TILE_T))   // 1024 work items

// ---------------------------------------------------------------------------
// Device scratch (no allocation allowed). uint4-typed => 16B alignment.
// ---------------------------------------------------------------------------
__device__ alignas(16) float g_pq[NB * NAD];
__device__ alignas(16) float g_score[NB * NT];
__device__ unsigned g_ticket;
// Pre-converted single-fp16 B operands: [chunk][a(128)][k(32)] packed as uint4
__device__ uint4 g_B4[NCHUNK * TILE_T * KCH / 8];
__device__ uint4 g_Wl4[TILE_T * KCH / 8];

// ---------------------------------------------------------------------------
// Shared memory: single-fp16 A and B tiles, double-buffered.
// ---------------------------------------------------------------------------
struct ScoreSmem {
    alignas(16) unsigned short A[2][TILE_T * ASTR];
    alignas(16) unsigned short B[2][TILE_T * ASTR];
    float pqc[NAD];
    float vw[NAD];
    float al[2][TILE_T + NKW - 1];
    float ws[NF * 2 * NKW];     // 1984 floats
    float cb[NF];
    float part[2][TILE_T];
    unsigned ticket;
};
static_assert(sizeof(ScoreSmem) <= 64 * 1024, "smem overflow");

// ---------------------------------------------------------------------------
// Helpers
// ---------------------------------------------------------------------------
__device__ __forceinline__ uint32_t smem_u32(const void* p) {
    uint32_t r;
    asm("{ .reg .u64 t; cvta.to.shared.u64 t, %1; cvt.u32.u64 %0, t; }"
        : "=r"(r) : "l"(p));
    return r;
}

__device__ __forceinline__ void ldsm4(uint32_t* r, uint32_t addr) {
    asm volatile("ldmatrix.sync.aligned.m8n8.x4.shared.b16 {%0,%1,%2,%3}, [%4];"
                 : "=r"(r[0]), "=r"(r[1]), "=r"(r[2]), "=r"(r[3]) : "r"(addr));
}

__device__ __forceinline__ void mma16816(float* c, const uint32_t* a,
                                         const uint32_t* b) {
    asm volatile(
        "mma.sync.aligned.m16n8k16.row.col.f32.f16.f16.f32 "
        "{%0,%1,%2,%3}, {%4,%5,%6,%7}, {%8,%9}, {%0,%1,%2,%3};"
        : "+f"(c[0]), "+f"(c[1]), "+f"(c[2]), "+f"(c[3])
        : "r"(a[0]), "r"(a[1]), "r"(a[2]), "r"(a[3]), "r"(b[0]), "r"(b[1]));
}

#define CP_ASYNC16(dst_u32, src_ptr) \
    asm volatile("cp.async.cg.shared.global [%0], [%1], 16;" \
                 :: "r"(dst_u32), "l"(src_ptr))
#define CP_COMMIT() asm volatile("cp.async.commit_group;")
#define CP_WAIT0()  asm volatile("cp.async.wait_group 0;")

__device__ __forceinline__ float tanh_fast(float x) {
    x = fminf(fmaxf(x, -20.f), 20.f);
    float e = __expf(-2.f * x);
    return __fdividef(1.f - e, 1.f + e);
}

// ---------------------------------------------------------------------------
// Prep: convert Wm / Wl to fp16, [chunk][a][k] linear layout
// ---------------------------------------------------------------------------
__global__ void prep_kernel(const float* __restrict__ Wm,
                            const float* __restrict__ Wl) {
    int idx = blockIdx.x * blockDim.x + threadIdx.x;
    unsigned short* bp = (unsigned short*)g_B4;
    unsigned short* wp = (unsigned short*)g_Wl4;
    if (idx < NMD * NAD) {
        int k = idx >> 7, a = idx & 127;
        int c = k >> 5, kk = k & 31;
        __half h = __float2half_rn(Wm[k * NAD + a]);
        bp[c * (TILE_T * KCH) + a * KCH + kk] = ((__half_raw)h).x;
    } else if (idx < NMD * NAD + TILE_T * KCH) {
        int r = idx - NMD * NAD;
        int a = r >> 5, kk = r & 31;
        __half h = __float2half_rn(Wl[kk * NAD + a]);   // kk < 32 == NF
        wp[a * KCH + kk] = ((__half_raw)h).x;
    }
}

// ---------------------------------------------------------------------------
// Kernel 1: processed query + ticket reset + ctx zeroing (folded)
// ---------------------------------------------------------------------------
__global__ void pq_kernel(const float* __restrict__ query,
                          const float* __restrict__ Wq,
                          const float* __restrict__ bq,
                          float* __restrict__ ctx) {
    __shared__ float qs[NQD];
    __shared__ float partial[256];
    int b = blockIdx.x;
    int tid = threadIdx.x;
    if (b == 0 && tid == 0) g_ticket = 0;
    ctx[b * NMD + tid]       = 0.f;
    ctx[b * NMD + 256 + tid] = 0.f;
    for (int i = tid; i < NQD; i += 256)
        qs[i] = query[b * NQD + i];
    __syncthreads();
    int a = tid & 127;
    int h = tid >> 7;
    float acc = 0.f;
    int q0 = h * (NQD / 2);
#pragma unroll 8
    for (int q = 0; q < NQD / 2; q++)
        acc = fmaf(qs[q0 + q], Wq[(q0 + q) * NAD + a], acc);
    partial[tid] = acc;
    __syncthreads();
    if (tid < 128)
        g_pq[b * NAD + a] = bq[a] + partial[tid] + partial[tid + 128];
}

// ---------------------------------------------------------------------------
// Kernel 2: PERSISTENT fused score kernel, single-fp16 1-product GEMM.
// 17 uniform chunks (16 memory + 1 fused location-conv), double-buffered
// cp.async B + reg-prefetched A, ldmatrix + mma.sync fp16.
// ---------------------------------------------------------------------------
__global__ __launch_bounds__(256, 2)
void score_kernel(const float* __restrict__ memory,
                  const float* __restrict__ alignments,
                  const unsigned char* __restrict__ mask,
                  const float* __restrict__ bm,
                  const float* __restrict__ conv_w,
                  const float* __restrict__ conv_b,
                  const float* __restrict__ bl,
                  const float* __restrict__ v_w,
                  const float* __restrict__ v_b) {
    extern __shared__ char smem_raw[];
    ScoreSmem& S = *reinterpret_cast<ScoreSmem*>(smem_raw);

    const int tid  = threadIdx.x;
    const int lane = tid & 31;
    const int wid  = tid >> 5;
    const int wm   = wid >> 2;
    const int wn   = wid & 3;
    const int g    = lane >> 2;
    const int tg   = lane & 3;

    const int tA = tid >> 2;
    const int gA = tid & 3;

    for (int i = tid; i < NF * 2 * NKW; i += 256) S.ws[i] = conv_w[i];
    if (tid < NF) S.cb[tid] = conv_b[tid];
    const float vb = *v_b;

    const uint32_t uA[2] = {smem_u32(S.A[0]), smem_u32(S.A[1])};
    const uint32_t uB[2] = {smem_u32(S.B[0]), smem_u32(S.B[1])};

    // cp.async: 2 units of 8 halfs per thread (512 uint4 per tile)
    const int iB0 = tid, iB1 = tid + 256;
    const uint32_t offB0 = (uint32_t)(((iB0 >> 2) * ASTR + (iB0 & 3) * 8) * 2);
    const uint32_t offB1 = (uint32_t)(((iB1 >> 2) * ASTR + (iB1 & 3) * 8) * 2);

    // ldmatrix per-lane addressing
    const int aRow  = wm * 64 + (lane & 15);
    const int aColX = (lane >> 4) * 8;
    const int bRow  = wn * 32 + ((lane >> 4) << 3) + (lane & 7);
    const int bColX = ((lane >> 3) & 1) * 8;

    float4 a4[2][2];
    const float* memb = memory;

    auto convertA = [&](int buf) {
#pragma unroll
        for (int u = 0; u < 2; u++) {
            __half2 h0 = __floats2half2_rn(a4[u][0].x, a4[u][0].y);
            __half2 h1 = __floats2half2_rn(a4[u][0].z, a4[u][0].w);
            __half2 h2 = __floats2half2_rn(a4[u][1].x, a4[u][1].y);
            __half2 h3 = __floats2half2_rn(a4[u][1].z, a4[u][1].w);
            int off = (tA + u * 64) * ASTR + gA * 8;
            *(uint4*)&S.A[buf][off] = make_uint4(
                *(uint32_t*)&h0, *(uint32_t*)&h1,
                *(uint32_t*)&h2, *(uint32_t*)&h3);
        }
    };
    auto loadA = [&](int c) {
#pragma unroll
        for (int u = 0; u < 2; u++) {
            const float* src = memb + (size_t)(tA + u * 64) * NMD + c * KCH + gA * 8;
            a4[u][0] = *(const float4*)src;
            a4[u][1] = *(const float4*)(src + 4);
        }
    };
    auto stageB = [&](int c) {
        const uint4* sp = (c < NCHUNK) ? (g_B4 + c * 512) : g_Wl4;
        const int nb = c & 1;
        CP_ASYNC16(uB[nb] + offB0, sp + iB0);
        CP_ASYNC16(uB[nb] + offB1, sp + iB1);
        CP_COMMIT();
    };

    // One K16 MMA step, single product
    auto mmaStep = [&](float acc[4][4][4], int k0, uint32_t uAh, uint32_t uBh) {
        uint32_t bf[8];
        uint32_t ab = uBh + (uint32_t)((bRow * ASTR + k0 + bColX) * 2);
        ldsm4(bf,     ab);
        ldsm4(bf + 4, ab + 16 * ASTR * 2);
#pragma unroll
        for (int mi = 0; mi < 4; mi++) {
            uint32_t aoff = (uint32_t)(((aRow + mi * 16) * ASTR + k0 + aColX) * 2);
            uint32_t af[4];
            ldsm4(af, uAh + aoff);
#pragma unroll
            for (int ni = 0; ni < 4; ni++)
                mma16816(acc[mi][ni], af, &bf[ni * 2]);
        }
    };

    // ======================= persistent tile loop =======================
    while (true) {
        if (tid == 0) S.ticket = atomicAdd(&g_ticket, 1u);
        __syncthreads();                 // publish ticket; fence prev tile
        const unsigned tile = S.ticket;
        if (tile >= NTILES) break;
        const int b  = (int)(tile >> 5);
        const int t0 = (int)(tile & 31) * TILE_T;

        for (int i = tid; i < 2 * (TILE_T + NKW - 1); i += 256) {
            int c = i / (TILE_T + NKW - 1);
            int p = i % (TILE_T + NKW - 1);
            int t = t0 - NPAD + p;
            S.al[c][p] = (t >= 0 && t < NT)
                       ? alignments[((size_t)b * NT + t) * 2 + c] : 0.f;
        }
        if (tid < NAD) {
            S.pqc[tid] = g_pq[b * NAD + tid] + bm[tid] + bl[tid];
            S.vw[tid]  = v_w[tid];
        }
        memb = memory + ((size_t)b * NT + t0) * NMD;

        float acc[4][4][4];
#pragma unroll
        for (int mi = 0; mi < 4; mi++)
#pragma unroll
            for (int ni = 0; ni < 4; ni++)
#pragma unroll
                for (int j = 0; j < 4; j++) acc[mi][ni][j] = 0.f;

        stageB(0);
        loadA(0);
        convertA(0);
        loadA(1);

        // --- 17 uniform chunks (chunk 16 == fused location conv) ---
        for (int c = 0; c <= NCHUNK; c++) {
            const int nc = c + 1;
            CP_WAIT0();
            __syncthreads();   // publish B(c)+A(c); fence MMA(c-1) reads
            const uint32_t uAh = uA[c & 1];
            const uint32_t uBh = uB[c & 1];
            // ks0
            mmaStep(acc, 0, uAh, uBh);
            // middle: stage/convert next chunk (fills tensor-idle slots)
            if (nc <= NCHUNK) {
                stageB(nc);
                if (nc < NCHUNK) {
                    convertA(nc & 1);
                    if (nc + 1 < NCHUNK) loadA(nc + 1);
                } else {
                    // loc chunk A: conv -> fp16 into A[0] (16&1 == 0)
                    for (int idx = tid; idx < TILE_T * NF; idx += 256) {
                        int t = idx >> 5, f = idx & 31;
                        float v = S.cb[f];
                        const float* wf = &S.ws[f * 2 * NKW];
#pragma unroll
                        for (int cc = 0; cc < 2; cc++)
#pragma unroll
                            for (int k = 0; k < NKW; k++)
                                v = fmaf(S.al[cc][t + k], wf[cc * NKW + k], v);
                        __half h = __float2half_rn(v);
                        S.A[0][t * ASTR + f] = ((__half_raw)h).x;
                    }
                }
            }
            // ks1
            mmaStep(acc, 16, uAh, uBh);
        }

        // Epilogue: tanh + v-dot, lane-group reduce, 2-stage warp reduce
        float s0[4], s1[4];
#pragma unroll
        for (int mi = 0; mi < 4; mi++) {
            float p0 = 0.f, p1 = 0.f;
#pragma unroll
            for (int ni = 0; ni < 4; ni++) {
#pragma unroll
                for (int j = 0; j < 2; j++) {
                    int cdx = wn * 32 + ni * 8 + tg * 2 + j;
                    p0 = fmaf(S.vw[cdx], tanh_fast(acc[mi][ni][j]     + S.pqc[cdx]), p0);
                    p1 = fmaf(S.vw[cdx], tanh_fast(acc[mi][ni][2 + j] + S.pqc[cdx]), p1);
                }
            }
            p0 += __shfl_xor_sync(0xffffffffu, p0, 1);
            p0 += __shfl_xor_sync(0xffffffffu, p0, 2);
            p1 += __shfl_xor_sync(0xffffffffu, p1, 1);
            p1 += __shfl_xor_sync(0xffffffffu, p1, 2);
            s0[mi] = p0;
            s1[mi] = p1;
        }
        __syncthreads();
        if (wn < 2 && tg == 0) {
#pragma unroll
            for (int mi = 0; mi < 4; mi++) {
                int r = wm * 64 + mi * 16 + g;
                S.part[wn][r]     = s0[mi];
                S.part[wn][r + 8] = s1[mi];
            }
        }
        __syncthreads();
        if (wn >= 2 && tg == 0) {
#pragma unroll
            for (int mi = 0; mi < 4; mi++) {
                int r = wm * 64 + mi * 16 + g;
                S.part[wn - 2][r]     += s0[mi];
                S.part[wn - 2][r + 8] += s1[mi];
            }
        }
        __syncthreads();

        if (tid < TILE_T) {
            float sc = S.part[0][tid] + S.part[1][tid] + vb;
            if (mask[(size_t)b * NT + t0 + tid]) sc = -CUDART_INF_F;
            g_score[(size_t)b * NT + t0 + tid] = sc;
        }
    }
}

// ---------------------------------------------------------------------------
// Kernel 3: row softmax over T -> alignment (float4, 1024 threads)
// ---------------------------------------------------------------------------
__global__ void softmax_kernel(float* __restrict__ align_out) {
    int b = blockIdx.x;
    int tid = threadIdx.x;
    __shared__ float red[1024];

    const float4* row = (const float4*)&g_score[(size_t)b * NT];
    float4 v = row[tid];
    float m = fmaxf(fmaxf(v.x, v.y), fmaxf(v.z, v.w));
    red[tid] = m;
    __syncthreads();
    for (int s = 512; s > 0; s >>= 1) {
        if (tid < s) red[tid] = fmaxf(red[tid], red[tid + s]);
        __syncthreads();
    }
    m = red[0];
    __syncthreads();

    float4 e;
    e.x = expf(v.x - m);
    e.y = expf(v.y - m);
    e.z = expf(v.z - m);
    e.w = expf(v.w - m);
    red[tid] = e.x + e.y + e.z + e.w;
    __syncthreads();
    for (int s = 512; s > 0; s >>= 1) {
        if (tid < s) red[tid] += red[tid + s];
        __syncthreads();
    }
    float inv = 1.0f / red[0];
    e.x *= inv; e.y *= inv; e.z *= inv; e.w *= inv;
    ((float4*)&align_out[(size_t)b * NT])[tid] = e;
}

// ---------------------------------------------------------------------------
// Kernel 4: context (float4 vectorized, 2 t-halves x 128 m-quads)
// ---------------------------------------------------------------------------
#define TCH 256
__global__ void context_kernel(const float* __restrict__ memory,
                               const float* __restrict__ align,
                               float* __restrict__ ctx) {
    int b  = blockIdx.y;
    int tc = blockIdx.x;
    int m4 = threadIdx.x & 127;
    int th = threadIdx.x >> 7;

    __shared__ float al[TCH];
    __shared__ float4 red[128];
    if (threadIdx.x < TCH)
        al[threadIdx.x] = align[(size_t)b * NT + tc * TCH + threadIdx.x];
    __syncthreads();

    const float4* mb = (const float4*)(memory +
        (size_t)b * NT * NMD + (size_t)(tc * TCH + th * 128) * NMD);
    float4 acc = make_float4(0.f, 0.f, 0.f, 0.f);
    const float* alh = &al[th * 128];
#pragma unroll 4
    for (int t = 0; t < 128; t++) {
        float a = alh[t];
        float4 v = mb[(size_t)t * 128 + m4];
        acc.x = fmaf(a, v.x, acc.x);
        acc.y = fmaf(a, v.y, acc.y);
        acc.z = fmaf(a, v.z, acc.z);
        acc.w = fmaf(a, v.w, acc.w);
    }
    if (th == 1) red[m4] = acc;
    __syncthreads();
    if (th == 0) {
        float4 o = red[m4];
        acc.x += o.x; acc.y += o.y; acc.z += o.z; acc.w += o.w;
        float* dst = &ctx[b * NMD + m4 * 4];
        atomicAdd(dst + 0, acc.x);
        atomicAdd(dst + 1, acc.y);
        atomicAdd(dst + 2, acc.z);
        atomicAdd(dst + 3, acc.w);
    }
}

// ---------------------------------------------------------------------------
// kernel_launch
// ---------------------------------------------------------------------------
extern "C" void kernel_launch(void* const* d_in, const int* in_sizes, int n_in,
                              void* d_out, int out_size) {
    const float* query      = (const float*)d_in[0];
    const float* memory     = (const float*)d_in[1];
    const float* alignments = (const float*)d_in[2];
    const unsigned char* mask = (const unsigned char*)d_in[3];
    const float* Wq     = (const float*)d_in[4];
    const float* bq     = (const float*)d_in[5];
    const float* Wm     = (const float*)d_in[6];
    const float* bm     = (const float*)d_in[7];
    const float* conv_w = (const float*)d_in[8];
    const float* conv_b = (const float*)d_in[9];
    const float* Wl     = (const float*)d_in[10];
    const float* bl     = (const float*)d_in[11];
    const float* v_w    = (const float*)d_in[12];
    const float* v_b    = (const float*)d_in[13];

    float* out       = (float*)d_out;
    float* out_ctx   = out;                // [NB, NMD]
    float* out_align = out + NB * NMD;     // [NB, NT]

    static int nblocks = 0;
    if (!nblocks) {
        cudaFuncSetAttribute(score_kernel,
                             cudaFuncAttributeMaxDynamicSharedMemorySize,
                             (int)sizeof(ScoreSmem));
        int sm = 148;
        cudaDeviceGetAttribute(&sm, cudaDevAttrMultiProcessorCount, 0);
        nblocks = 2 * sm;
    }

    prep_kernel<<<(NMD * NAD + TILE_T * KCH + 255) / 256, 256>>>(Wm, Wl);
    pq_kernel<<<NB, 256>>>(query, Wq, bq, out_ctx);
    score_kernel<<<nblocks, 256, sizeof(ScoreSmem)>>>(
        memory, alignments, mask, bm, conv_w, conv_b, bl, v_w, v_b);
    softmax_kernel<<<NB, 1024>>>(out_align);
    context_kernel<<<dim3(NT / TCH, NB), 256>>>(memory, out_align, out_ctx);
}

// round 13
// speedup vs baseline: 3.8739x; 1.0186x over previous
#include <cuda_runtime.h>
#include <cuda_fp16.h>
#include <math.h>
#include <math_constants.h>
#include <stdint.h>

// Problem constants
#define NB   32
#define NT   4096
#define NQD  1024
#define NMD  512
#define NAD  128
#define NF   32
#define NKW  31
#define NPAD 15

// Score-kernel tiling
#define TILE_T  128
#define KCH     64          // K per chunk; loc chunk (chunk 8) uses cols 0..31
#define NCHUNK  8
#define ASTR    72          // padded row stride in elems (144 B, 16B-multiple)
#define NTILES  (NB * (NT / TILE_T))   // 1024 work items

// ---------------------------------------------------------------------------
// Device scratch (no allocation allowed). uint4-typed => 16B alignment.
// ---------------------------------------------------------------------------
__device__ alignas(16) float g_pq[NB * NAD];
__device__ alignas(16) float g_score[NB * NT];
__device__ unsigned g_ticket;
// fp16 B operands: [chunk][a(128)][k(64)] packed as uint4 (8 halfs)
__device__ uint4 g_B4[NCHUNK * TILE_T * KCH / 8];
__device__ uint4 g_Wl4[TILE_T * KCH / 8];   // cols 32..63 zero

// ---------------------------------------------------------------------------
// Shared memory: fp16 A and B tiles, double-buffered, KCH=64.
// ---------------------------------------------------------------------------
struct ScoreSmem {
    alignas(16) unsigned short A[2][TILE_T * ASTR];
    alignas(16) unsigned short B[2][TILE_T * ASTR];
    float pqc[NAD];
    float vw[NAD];
    float al[2][TILE_T + NKW - 1];
    float ws[NF * 2 * NKW];     // 1984 floats
    float cb[NF];
    float part[2][TILE_T];
    unsigned ticket;
};
static_assert(sizeof(ScoreSmem) <= 100 * 1024, "smem overflow");

// ---------------------------------------------------------------------------
// Helpers
// ---------------------------------------------------------------------------
__device__ __forceinline__ uint32_t smem_u32(const void* p) {
    uint32_t r;
    asm("{ .reg .u64 t; cvta.to.shared.u64 t, %1; cvt.u32.u64 %0, t; }"
        : "=r"(r) : "l"(p));
    return r;
}

__device__ __forceinline__ void ldsm4(uint32_t* r, uint32_t addr) {
    asm volatile("ldmatrix.sync.aligned.m8n8.x4.shared.b16 {%0,%1,%2,%3}, [%4];"
                 : "=r"(r[0]), "=r"(r[1]), "=r"(r[2]), "=r"(r[3]) : "r"(addr));
}

__device__ __forceinline__ void mma16816(float* c, const uint32_t* a,
                                         const uint32_t* b) {
    asm volatile(
        "mma.sync.aligned.m16n8k16.row.col.f32.f16.f16.f32 "
        "{%0,%1,%2,%3}, {%4,%5,%6,%7}, {%8,%9}, {%0,%1,%2,%3};"
        : "+f"(c[0]), "+f"(c[1]), "+f"(c[2]), "+f"(c[3])
        : "r"(a[0]), "r"(a[1]), "r"(a[2]), "r"(a[3]), "r"(b[0]), "r"(b[1]));
}

#define CP_ASYNC16(dst_u32, src_ptr) \
    asm volatile("cp.async.cg.shared.global [%0], [%1], 16;" \
                 :: "r"(dst_u32), "l"(src_ptr))
#define CP_COMMIT() asm volatile("cp.async.commit_group;")
#define CP_WAIT0()  asm volatile("cp.async.wait_group 0;")

__device__ __forceinline__ float tanh_fast(float x) {
    x = fminf(fmaxf(x, -20.f), 20.f);
    float e = __expf(-2.f * x);
    return __fdividef(1.f - e, 1.f + e);
}

// ---------------------------------------------------------------------------
// Prep: convert Wm / Wl to fp16, [chunk][a][k64] layout; Wl cols>=32 zeroed
// ---------------------------------------------------------------------------
__global__ void prep_kernel(const float* __restrict__ Wm,
                            const float* __restrict__ Wl) {
    int idx = blockIdx.x * blockDim.x + threadIdx.x;
    unsigned short* bp = (unsigned short*)g_B4;
    unsigned short* wp = (unsigned short*)g_Wl4;
    if (idx < NMD * NAD) {
        int k = idx >> 7, a = idx & 127;
        int c = k >> 6, kk = k & 63;
        __half h = __float2half_rn(Wm[k * NAD + a]);
        bp[c * (TILE_T * KCH) + a * KCH + kk] = ((__half_raw)h).x;
    } else if (idx < NMD * NAD + TILE_T * KCH) {
        int r = idx - NMD * NAD;
        int a = r >> 6, kk = r & 63;
        float v = (kk < NF) ? Wl[kk * NAD + a] : 0.0f;
        __half h = __float2half_rn(v);
        wp[a * KCH + kk] = ((__half_raw)h).x;
    }
}

// ---------------------------------------------------------------------------
// Kernel 1: processed query + ticket reset + ctx zeroing (folded)
// ---------------------------------------------------------------------------
__global__ void pq_kernel(const float* __restrict__ query,
                          const float* __restrict__ Wq,
                          const float* __restrict__ bq,
                          float* __restrict__ ctx) {
    __shared__ float qs[NQD];
    __shared__ float partial[256];
    int b = blockIdx.x;
    int tid = threadIdx.x;
    if (b == 0 && tid == 0) g_ticket = 0;
    ctx[b * NMD + tid]       = 0.f;
    ctx[b * NMD + 256 + tid] = 0.f;
    for (int i = tid; i < NQD; i += 256)
        qs[i] = query[b * NQD + i];
    __syncthreads();
    int a = tid & 127;
    int h = tid >> 7;
    float acc = 0.f;
    int q0 = h * (NQD / 2);
#pragma unroll 8
    for (int q = 0; q < NQD / 2; q++)
        acc = fmaf(qs[q0 + q], Wq[(q0 + q) * NAD + a], acc);
    partial[tid] = acc;
    __syncthreads();
    if (tid < 128)
        g_pq[b * NAD + a] = bq[a] + partial[tid] + partial[tid + 128];
}

// ---------------------------------------------------------------------------
// Kernel 2: PERSISTENT fused score kernel, fp16 GEMM, KCH=64 (9 chunks).
// Double-buffered cp.async B + half-staged register-prefetched A;
// stage/convert interleaved among 4 K16 steps per chunk.
// ---------------------------------------------------------------------------
__global__ __launch_bounds__(256, 2)
void score_kernel(const float* __restrict__ memory,
                  const float* __restrict__ alignments,
                  const unsigned char* __restrict__ mask,
                  const float* __restrict__ bm,
                  const float* __restrict__ conv_w,
                  const float* __restrict__ conv_b,
                  const float* __restrict__ bl,
                  const float* __restrict__ v_w,
                  const float* __restrict__ v_b) {
    extern __shared__ char smem_raw[];
    ScoreSmem& S = *reinterpret_cast<ScoreSmem*>(smem_raw);

    const int tid  = threadIdx.x;
    const int lane = tid & 31;
    const int wid  = tid >> 5;
    const int wm   = wid >> 2;
    const int wn   = wid & 3;
    const int g    = lane >> 2;
    const int tg   = lane & 3;

    for (int i = tid; i < NF * 2 * NKW; i += 256) S.ws[i] = conv_w[i];
    if (tid < NF) S.cb[tid] = conv_b[tid];
    const float vb = *v_b;

    const uint32_t uA[2] = {smem_u32(S.A[0]), smem_u32(S.A[1])};
    const uint32_t uB[2] = {smem_u32(S.B[0]), smem_u32(S.B[1])};

    // ldmatrix per-lane addressing
    const int aRow  = wm * 64 + (lane & 15);
    const int aColX = (lane >> 4) * 8;
    const int bRow  = wn * 32 + ((lane >> 4) << 3) + (lane & 7);
    const int bColX = ((lane >> 3) & 1) * 8;

    float4 a4[2][2];     // one half-chunk (16 floats)
    const float* memb = memory;

    // A staging: unit = tid + (2h+u)*256, u in {0,1}; t = unit>>3, g8 = unit&7
    auto loadA_half = [&](int c, int h) {
#pragma unroll
        for (int u = 0; u < 2; u++) {
            int unit = tid + (2 * h + u) * 256;
            int t = unit >> 3, g8 = unit & 7;
            const float* src = memb + (size_t)t * NMD + c * KCH + g8 * 8;
            a4[u][0] = *(const float4*)src;
            a4[u][1] = *(const float4*)(src + 4);
        }
    };
    auto convertA_half = [&](int buf, int h) {
#pragma unroll
        for (int u = 0; u < 2; u++) {
            int unit = tid + (2 * h + u) * 256;
            int t = unit >> 3, g8 = unit & 7;
            __half2 h0 = __floats2half2_rn(a4[u][0].x, a4[u][0].y);
            __half2 h1 = __floats2half2_rn(a4[u][0].z, a4[u][0].w);
            __half2 h2 = __floats2half2_rn(a4[u][1].x, a4[u][1].y);
            __half2 h3 = __floats2half2_rn(a4[u][1].z, a4[u][1].w);
            *(uint4*)&S.A[buf][t * ASTR + g8 * 8] = make_uint4(
                *(uint32_t*)&h0, *(uint32_t*)&h1,
                *(uint32_t*)&h2, *(uint32_t*)&h3);
        }
    };
    // B staging: 1024 uint4 per tile, 4 per thread
    auto stageB = [&](int c) {
        const uint4* sp = (c < NCHUNK) ? (g_B4 + c * 1024) : g_Wl4;
        const int nb = c & 1;
#pragma unroll
        for (int u = 0; u < 4; u++) {
            int i = tid + u * 256;
            uint32_t off = (uint32_t)(((i >> 3) * ASTR + (i & 7) * 8) * 2);
            CP_ASYNC16(uB[nb] + off, sp + i);
        }
        CP_COMMIT();
    };
    // One K16 MMA step
    auto mmaStep = [&](float acc[4][4][4], int k0, uint32_t uAh, uint32_t uBh) {
        uint32_t bf[8];
        uint32_t ab = uBh + (uint32_t)((bRow * ASTR + k0 + bColX) * 2);
        ldsm4(bf,     ab);
        ldsm4(bf + 4, ab + 16 * ASTR * 2);
#pragma unroll
        for (int mi = 0; mi < 4; mi++) {
            uint32_t aoff = (uint32_t)(((aRow + mi * 16) * ASTR + k0 + aColX) * 2);
            uint32_t af[4];
            ldsm4(af, uAh + aoff);
#pragma unroll
            for (int ni = 0; ni < 4; ni++)
                mma16816(acc[mi][ni], af, &bf[ni * 2]);
        }
    };
    // Location conv fill: A cols 0..31 of buffer 0 (stale cols 32..63 hit
    // zero B columns; stale values are finite fp16, so products are exact 0)
    auto locFill = [&]() {
        for (int idx = tid; idx < TILE_T * NF; idx += 256) {
            int t = idx >> 5, f = idx & 31;
            float v = S.cb[f];
            const float* wf = &S.ws[f * 2 * NKW];
#pragma unroll
            for (int cc = 0; cc < 2; cc++)
#pragma unroll
                for (int k = 0; k < NKW; k++)
                    v = fmaf(S.al[cc][t + k], wf[cc * NKW + k], v);
            __half h = __float2half_rn(v);
            S.A[0][t * ASTR + f] = ((__half_raw)h).x;
        }
    };

    // ======================= persistent tile loop =======================
    while (true) {
        if (tid == 0) S.ticket = atomicAdd(&g_ticket, 1u);
        __syncthreads();                 // publish ticket; fence prev tile
        const unsigned tile = S.ticket;
        if (tile >= NTILES) break;
        const int b  = (int)(tile >> 5);
        const int t0 = (int)(tile & 31) * TILE_T;

        for (int i = tid; i < 2 * (TILE_T + NKW - 1); i += 256) {
            int c = i / (TILE_T + NKW - 1);
            int p = i % (TILE_T + NKW - 1);
            int t = t0 - NPAD + p;
            S.al[c][p] = (t >= 0 && t < NT)
                       ? alignments[((size_t)b * NT + t) * 2 + c] : 0.f;
        }
        if (tid < NAD) {
            S.pqc[tid] = g_pq[b * NAD + tid] + bm[tid] + bl[tid];
            S.vw[tid]  = v_w[tid];
        }
        memb = memory + ((size_t)b * NT + t0) * NMD;

        float acc[4][4][4];
#pragma unroll
        for (int mi = 0; mi < 4; mi++)
#pragma unroll
            for (int ni = 0; ni < 4; ni++)
#pragma unroll
                for (int j = 0; j < 4; j++) acc[mi][ni][j] = 0.f;

        // Prologue: fully stage chunk 0; prefetch half0 of chunk 1
        stageB(0);
        loadA_half(0, 0);
        convertA_half(0, 0);
        loadA_half(0, 1);
        convertA_half(0, 1);
        loadA_half(1, 0);

        // --- 9 chunks (chunk 8 == fused location conv) ---
        for (int c = 0; c <= NCHUNK; c++) {
            const int nc = c + 1;
            CP_WAIT0();
            __syncthreads();   // publish B(c)+A(c); fence MMA(c-1) reads
            const uint32_t uAh = uA[c & 1];
            const uint32_t uBh = uB[c & 1];

            mmaStep(acc, 0, uAh, uBh);
            if (nc <= NCHUNK) {
                stageB(nc);
                if (nc < NCHUNK) {
                    convertA_half(nc & 1, 0);   // from a4 (prefetched)
                    loadA_half(nc, 1);
                } else {
                    locFill();                  // chunk 8 A (buffer 0)
                }
            }
            mmaStep(acc, 16, uAh, uBh);
            mmaStep(acc, 32, uAh, uBh);
            if (nc < NCHUNK) {
                convertA_half(nc & 1, 1);
                if (nc + 1 < NCHUNK) loadA_half(nc + 1, 0);
            }
            mmaStep(acc, 48, uAh, uBh);
        }

        // Epilogue: tanh + v-dot, lane-group reduce, 2-stage warp reduce
        float s0[4], s1[4];
#pragma unroll
        for (int mi = 0; mi < 4; mi++) {
            float p0 = 0.f, p1 = 0.f;
#pragma unroll
            for (int ni = 0; ni < 4; ni++) {
#pragma unroll
                for (int j = 0; j < 2; j++) {
                    int cdx = wn * 32 + ni * 8 + tg * 2 + j;
                    p0 = fmaf(S.vw[cdx], tanh_fast(acc[mi][ni][j]     + S.pqc[cdx]), p0);
                    p1 = fmaf(S.vw[cdx], tanh_fast(acc[mi][ni][2 + j] + S.pqc[cdx]), p1);
                }
            }
            p0 += __shfl_xor_sync(0xffffffffu, p0, 1);
            p0 += __shfl_xor_sync(0xffffffffu, p0, 2);
            p1 += __shfl_xor_sync(0xffffffffu, p1, 1);
            p1 += __shfl_xor_sync(0xffffffffu, p1, 2);
            s0[mi] = p0;
            s1[mi] = p1;
        }
        __syncthreads();
        if (wn < 2 && tg == 0) {
#pragma unroll
            for (int mi = 0; mi < 4; mi++) {
                int r = wm * 64 + mi * 16 + g;
                S.part[wn][r]     = s0[mi];
                S.part[wn][r + 8] = s1[mi];
            }
        }
        __syncthreads();
        if (wn >= 2 && tg == 0) {
#pragma unroll
            for (int mi = 0; mi < 4; mi++) {
                int r = wm * 64 + mi * 16 + g;
                S.part[wn - 2][r]     += s0[mi];
                S.part[wn - 2][r + 8] += s1[mi];
            }
        }
        __syncthreads();

        if (tid < TILE_T) {
            float sc = S.part[0][tid] + S.part[1][tid] + vb;
            if (mask[(size_t)b * NT + t0 + tid]) sc = -CUDART_INF_F;
            g_score[(size_t)b * NT + t0 + tid] = sc;
        }
    }
}

// ---------------------------------------------------------------------------
// Kernel 3: row softmax over T -> alignment (float4, 1024 threads)
// ---------------------------------------------------------------------------
__global__ void softmax_kernel(float* __restrict__ align_out) {
    int b = blockIdx.x;
    int tid = threadIdx.x;
    __shared__ float red[1024];

    const float4* row = (const float4*)&g_score[(size_t)b * NT];
    float4 v = row[tid];
    float m = fmaxf(fmaxf(v.x, v.y), fmaxf(v.z, v.w));
    red[tid] = m;
    __syncthreads();
    for (int s = 512; s > 0; s >>= 1) {
        if (tid < s) red[tid] = fmaxf(red[tid], red[tid + s]);
        __syncthreads();
    }
    m = red[0];
    __syncthreads();

    float4 e;
    e.x = expf(v.x - m);
    e.y = expf(v.y - m);
    e.z = expf(v.z - m);
    e.w = expf(v.w - m);
    red[tid] = e.x + e.y + e.z + e.w;
    __syncthreads();
    for (int s = 512; s > 0; s >>= 1) {
        if (tid < s) red[tid] += red[tid + s];
        __syncthreads();
    }
    float inv = 1.0f / red[0];
    e.x *= inv; e.y *= inv; e.z *= inv; e.w *= inv;
    ((float4*)&align_out[(size_t)b * NT])[tid] = e;
}

// ---------------------------------------------------------------------------
// Kernel 4: context (float4 vectorized, 2 t-halves x 128 m-quads)
// ---------------------------------------------------------------------------
#define TCH 256
__global__ void context_kernel(const float* __restrict__ memory,
                               const float* __restrict__ align,
                               float* __restrict__ ctx) {
    int b  = blockIdx.y;
    int tc = blockIdx.x;
    int m4 = threadIdx.x & 127;
    int th = threadIdx.x >> 7;

    __shared__ float al[TCH];
    __shared__ float4 red[128];
    if (threadIdx.x < TCH)
        al[threadIdx.x] = align[(size_t)b * NT + tc * TCH + threadIdx.x];
    __syncthreads();

    const float4* mb = (const float4*)(memory +
        (size_t)b * NT * NMD + (size_t)(tc * TCH + th * 128) * NMD);
    float4 acc = make_float4(0.f, 0.f, 0.f, 0.f);
    const float* alh = &al[th * 128];
#pragma unroll 4
    for (int t = 0; t < 128; t++) {
        float a = alh[t];
        float4 v = mb[(size_t)t * 128 + m4];
        acc.x = fmaf(a, v.x, acc.x);
        acc.y = fmaf(a, v.y, acc.y);
        acc.z = fmaf(a, v.z, acc.z);
        acc.w = fmaf(a, v.w, acc.w);
    }
    if (th == 1) red[m4] = acc;
    __syncthreads();
    if (th == 0) {
        float4 o = red[m4];
        acc.x += o.x; acc.y += o.y; acc.z += o.z; acc.w += o.w;
        float* dst = &ctx[b * NMD + m4 * 4];
        atomicAdd(dst + 0, acc.x);
        atomicAdd(dst + 1, acc.y);
        atomicAdd(dst + 2, acc.z);
        atomicAdd(dst + 3, acc.w);
    }
}

// ---------------------------------------------------------------------------
// kernel_launch
// ---------------------------------------------------------------------------
extern "C" void kernel_launch(void* const* d_in, const int* in_sizes, int n_in,
                              void* d_out, int out_size) {
    const float* query      = (const float*)d_in[0];
    const float* memory     = (const float*)d_in[1];
    const float* alignments = (const float*)d_in[2];
    const unsigned char* mask = (const unsigned char*)d_in[3];
    const float* Wq     = (const float*)d_in[4];
    const float* bq     = (const float*)d_in[5];
    const float* Wm     = (const float*)d_in[6];
    const float* bm     = (const float*)d_in[7];
    const float* conv_w = (const float*)d_in[8];
    const float* conv_b = (const float*)d_in[9];
    const float* Wl     = (const float*)d_in[10];
    const float* bl     = (const float*)d_in[11];
    const float* v_w    = (const float*)d_in[12];
    const float* v_b    = (const float*)d_in[13];

    float* out       = (float*)d_out;
    float* out_ctx   = out;                // [NB, NMD]
    float* out_align = out + NB * NMD;     // [NB, NT]

    static int nblocks = 0;
    if (!nblocks) {
        cudaFuncSetAttribute(score_kernel,
                             cudaFuncAttributeMaxDynamicSharedMemorySize,
                             (int)sizeof(ScoreSmem));
        int sm = 148;
        cudaDeviceGetAttribute(&sm, cudaDevAttrMultiProcessorCount, 0);
        nblocks = 2 * sm;
    }

    prep_kernel<<<(NMD * NAD + TILE_T * KCH + 255) / 256, 256>>>(Wm, Wl);
    pq_kernel<<<NB, 256>>>(query, Wq, bq, out_ctx);
    score_kernel<<<nblocks, 256, sizeof(ScoreSmem)>>>(
        memory, alignments, mask, bm, conv_w, conv_b, bl, v_w, v_b);
    softmax_kernel<<<NB, 1024>>>(out_align);
    context_kernel<<<dim3(NT / TCH, NB), 256>>>(memory, out_align, out_ctx);
}